// round 5
// baseline (speedup 1.0000x reference)
#include <cuda_runtime.h>
#include <math.h>

// Problem constants
#define TOK    16384      // 8 * 2048 tokens
#define DMODEL 768
#define NEXP   4
#define FF     1024
#define TOPK   2

// GEMM tiling
#define BM 128
#define BN 128
#define BK 8
#define TM 8
#define TN 8
#define NTHREADS 256

// Static device scratch (allocations are forbidden)
__device__ float g_t[TOK * DMODEL];          // post-projection tokens  (~50 MB)
__device__ float g_hid[TOK * FF];            // per-expert hidden, reused sequentially (~67 MB)
__device__ int   g_idx[NEXP * TOK];          // gathered token ids per expert
__device__ float g_gate[NEXP * TOK];         // gate per gathered slot
__device__ int   g_cnt[NEXP];                // tokens per expert

__device__ __forceinline__ float gelu_tanh(float x) {
    // matches jax.nn.gelu(approximate=True)
    float u = 0.7978845608028654f * (x + 0.044715f * x * x * x);
    return 0.5f * x * (1.0f + tanhf(u));
}

// ---------------------------------------------------------------------------
// Kernel 0: reset per-launch state
// ---------------------------------------------------------------------------
__global__ void zero_cnt_kernel() {
    if (threadIdx.x < NEXP) g_cnt[threadIdx.x] = 0;
}

// ---------------------------------------------------------------------------
// Kernel 1: t = input @ W + b   (M=TOK, N=DMODEL, K=DMODEL)
// ---------------------------------------------------------------------------
__global__ __launch_bounds__(NTHREADS) void proj_kernel(
    const float* __restrict__ A,     // [TOK, DMODEL]
    const float* __restrict__ Bm,    // [DMODEL, DMODEL]
    const float* __restrict__ bias)  // [DMODEL]
{
    __shared__ float As[BK][BM];
    __shared__ float Bs[BK][BN];

    const int tid = threadIdx.x;
    const int rowBase = blockIdx.y * BM;
    const int colBase = blockIdx.x * BN;
    const int K = DMODEL, N = DMODEL;

    const int aRow = tid >> 1, aCol = (tid & 1) * 4;
    const int bRow = tid >> 5, bCol = (tid & 31) * 4;
    const int tx = tid & 15, ty = tid >> 4;

    float acc[TM][TN] = {};

    for (int k0 = 0; k0 < K; k0 += BK) {
        float4 av = *(const float4*)&A[(size_t)(rowBase + aRow) * K + k0 + aCol];
        As[aCol + 0][aRow] = av.x;
        As[aCol + 1][aRow] = av.y;
        As[aCol + 2][aRow] = av.z;
        As[aCol + 3][aRow] = av.w;
        *(float4*)&Bs[bRow][bCol] =
            *(const float4*)&Bm[(size_t)(k0 + bRow) * N + colBase + bCol];
        __syncthreads();

        #pragma unroll
        for (int kk = 0; kk < BK; kk++) {
            float a[TM], b[TN];
            #pragma unroll
            for (int i = 0; i < TM; i++) a[i] = As[kk][ty * TM + i];
            #pragma unroll
            for (int j = 0; j < TN; j++) b[j] = Bs[kk][tx * TN + j];
            #pragma unroll
            for (int i = 0; i < TM; i++)
                #pragma unroll
                for (int j = 0; j < TN; j++) acc[i][j] += a[i] * b[j];
        }
        __syncthreads();
    }

    #pragma unroll
    for (int i = 0; i < TM; i++) {
        int r = rowBase + ty * TM + i;
        #pragma unroll
        for (int j = 0; j < TN; j++) {
            int c = colBase + tx * TN + j;
            g_t[(size_t)r * DMODEL + c] = acc[i][j] + bias[c];
        }
    }
}

// ---------------------------------------------------------------------------
// Kernel 2: router — warp per token, top-2 of logits, renormalized gates,
//           build per-expert gather lists.
// ---------------------------------------------------------------------------
__global__ void router_kernel(const float* __restrict__ Wg,   // [DMODEL, NEXP]
                              const float* __restrict__ bg)   // [NEXP]
{
    int warp = (blockIdx.x * blockDim.x + threadIdx.x) >> 5;
    int lane = threadIdx.x & 31;
    if (warp >= TOK) return;

    const float* row = g_t + (size_t)warp * DMODEL;
    float l0 = 0.f, l1 = 0.f, l2 = 0.f, l3 = 0.f;
    for (int k = lane; k < DMODEL; k += 32) {
        float x = row[k];
        const float* w = Wg + k * NEXP;
        l0 += x * w[0]; l1 += x * w[1]; l2 += x * w[2]; l3 += x * w[3];
    }
    #pragma unroll
    for (int off = 16; off; off >>= 1) {
        l0 += __shfl_xor_sync(0xFFFFFFFFu, l0, off);
        l1 += __shfl_xor_sync(0xFFFFFFFFu, l1, off);
        l2 += __shfl_xor_sync(0xFFFFFFFFu, l2, off);
        l3 += __shfl_xor_sync(0xFFFFFFFFu, l3, off);
    }
    if (lane == 0) {
        float v[NEXP] = { l0 + bg[0], l1 + bg[1], l2 + bg[2], l3 + bg[3] };
        // top-1 (lowest index wins ties, matching lax.top_k)
        int i1 = 0;
        #pragma unroll
        for (int e = 1; e < NEXP; e++) if (v[e] > v[i1]) i1 = e;
        int i2 = -1;
        #pragma unroll
        for (int e = 0; e < NEXP; e++) {
            if (e == i1) continue;
            if (i2 < 0 || v[e] > v[i2]) i2 = e;
        }
        // softmax denominator cancels under top-k renormalization
        float gb = expf(v[i2] - v[i1]);   // <= 1
        float s = 1.0f + gb;
        float ga = 1.0f / s;
        gb = gb / s;

        int p1 = atomicAdd(&g_cnt[i1], 1);
        g_idx[i1 * TOK + p1]  = warp;
        g_gate[i1 * TOK + p1] = ga;
        int p2 = atomicAdd(&g_cnt[i2], 1);
        g_idx[i2 * TOK + p2]  = warp;
        g_gate[i2 * TOK + p2] = gb;
    }
}

// ---------------------------------------------------------------------------
// Kernel 3: per-expert FFN1 — hid = gelu(t[gather] @ W1_e + b1_e)
//           M = cnt[e] (dynamic), N = FF, K = DMODEL
// ---------------------------------------------------------------------------
__global__ __launch_bounds__(NTHREADS) void ffn1_kernel(
    const float* __restrict__ W1,   // [NEXP, DMODEL, FF]
    const float* __restrict__ b1,   // [NEXP, FF]
    int e)
{
    const int cnt = g_cnt[e];
    const int rowBase = blockIdx.y * BM;
    if (rowBase >= cnt) return;

    __shared__ float As[BK][BM];
    __shared__ float Bs[BK][BN];
    __shared__ int   Rows[BM];

    const int tid = threadIdx.x;
    if (tid < BM) {
        int r = rowBase + tid;
        Rows[tid] = (r < cnt) ? g_idx[e * TOK + r] : -1;
    }
    __syncthreads();

    const float* Bm = W1 + (size_t)e * DMODEL * FF;
    const int colBase = blockIdx.x * BN;
    const int K = DMODEL, N = FF;

    const int aRow = tid >> 1, aCol = (tid & 1) * 4;
    const int bRow = tid >> 5, bCol = (tid & 31) * 4;
    const int tx = tid & 15, ty = tid >> 4;

    float acc[TM][TN] = {};
    const int tokA = Rows[aRow];

    for (int k0 = 0; k0 < K; k0 += BK) {
        float4 av = (tokA >= 0)
            ? *(const float4*)&g_t[(size_t)tokA * DMODEL + k0 + aCol]
            : make_float4(0.f, 0.f, 0.f, 0.f);
        As[aCol + 0][aRow] = av.x;
        As[aCol + 1][aRow] = av.y;
        As[aCol + 2][aRow] = av.z;
        As[aCol + 3][aRow] = av.w;
        *(float4*)&Bs[bRow][bCol] =
            *(const float4*)&Bm[(size_t)(k0 + bRow) * N + colBase + bCol];
        __syncthreads();

        #pragma unroll
        for (int kk = 0; kk < BK; kk++) {
            float a[TM], b[TN];
            #pragma unroll
            for (int i = 0; i < TM; i++) a[i] = As[kk][ty * TM + i];
            #pragma unroll
            for (int j = 0; j < TN; j++) b[j] = Bs[kk][tx * TN + j];
            #pragma unroll
            for (int i = 0; i < TM; i++)
                #pragma unroll
                for (int j = 0; j < TN; j++) acc[i][j] += a[i] * b[j];
        }
        __syncthreads();
    }

    #pragma unroll
    for (int i = 0; i < TM; i++) {
        int r = rowBase + ty * TM + i;
        if (r >= cnt) continue;
        #pragma unroll
        for (int j = 0; j < TN; j++) {
            int c = colBase + tx * TN + j;
            g_hid[(size_t)r * FF + c] = gelu_tanh(acc[i][j] + b1[e * FF + c]);
        }
    }
}

// ---------------------------------------------------------------------------
// Kernel 4: per-expert FFN2 — out[tok] += gate * (hid @ W2_e + b2_e)
//           M = cnt[e], N = DMODEL, K = FF
// ---------------------------------------------------------------------------
__global__ __launch_bounds__(NTHREADS) void ffn2_kernel(
    const float* __restrict__ W2,   // [NEXP, FF, DMODEL]
    const float* __restrict__ b2,   // [NEXP, DMODEL]
    float* __restrict__ out,        // [TOK, DMODEL], pre-zeroed
    int e)
{
    const int cnt = g_cnt[e];
    const int rowBase = blockIdx.y * BM;
    if (rowBase >= cnt) return;

    __shared__ float As[BK][BM];
    __shared__ float Bs[BK][BN];
    __shared__ int   Rows[BM];
    __shared__ float Gates[BM];

    const int tid = threadIdx.x;
    if (tid < BM) {
        int r = rowBase + tid;
        Rows[tid]  = (r < cnt) ? g_idx[e * TOK + r] : -1;
        Gates[tid] = (r < cnt) ? g_gate[e * TOK + r] : 0.f;
    }
    __syncthreads();

    const float* Bm = W2 + (size_t)e * FF * DMODEL;
    const int colBase = blockIdx.x * BN;
    const int K = FF, N = DMODEL;

    const int aRow = tid >> 1, aCol = (tid & 1) * 4;
    const int bRow = tid >> 5, bCol = (tid & 31) * 4;
    const int tx = tid & 15, ty = tid >> 4;

    float acc[TM][TN] = {};

    for (int k0 = 0; k0 < K; k0 += BK) {
        // A is dense per-expert hidden (rows beyond cnt hold finite stale data;
        // their results are discarded below).
        float4 av = *(const float4*)&g_hid[(size_t)(rowBase + aRow) * FF + k0 + aCol];
        As[aCol + 0][aRow] = av.x;
        As[aCol + 1][aRow] = av.y;
        As[aCol + 2][aRow] = av.z;
        As[aCol + 3][aRow] = av.w;
        *(float4*)&Bs[bRow][bCol] =
            *(const float4*)&Bm[(size_t)(k0 + bRow) * N + colBase + bCol];
        __syncthreads();

        #pragma unroll
        for (int kk = 0; kk < BK; kk++) {
            float a[TM], b[TN];
            #pragma unroll
            for (int i = 0; i < TM; i++) a[i] = As[kk][ty * TM + i];
            #pragma unroll
            for (int j = 0; j < TN; j++) b[j] = Bs[kk][tx * TN + j];
            #pragma unroll
            for (int i = 0; i < TM; i++)
                #pragma unroll
                for (int j = 0; j < TN; j++) acc[i][j] += a[i] * b[j];
        }
        __syncthreads();
    }

    #pragma unroll
    for (int i = 0; i < TM; i++) {
        int lr = ty * TM + i;
        int r = rowBase + lr;
        if (r >= cnt) continue;
        int tok = Rows[lr];
        float gate = Gates[lr];
        #pragma unroll
        for (int j = 0; j < TN; j++) {
            int c = colBase + tx * TN + j;
            atomicAdd(&out[(size_t)tok * DMODEL + c],
                      gate * (acc[i][j] + b2[e * DMODEL + c]));
        }
    }
}

// ---------------------------------------------------------------------------
// Launch
// inputs (metadata order): input_ids, W, b, Wg, bg, W1, b1, W2, b2
// ---------------------------------------------------------------------------
extern "C" void kernel_launch(void* const* d_in, const int* in_sizes, int n_in,
                              void* d_out, int out_size) {
    const float* x   = (const float*)d_in[0];
    const float* W   = (const float*)d_in[1];
    const float* b   = (const float*)d_in[2];
    const float* Wg  = (const float*)d_in[3];
    const float* bg  = (const float*)d_in[4];
    const float* W1  = (const float*)d_in[5];
    const float* b1  = (const float*)d_in[6];
    const float* W2  = (const float*)d_in[7];
    const float* b2  = (const float*)d_in[8];
    float* out = (float*)d_out;

    // Output accumulates via atomics — zero it (poisoned 0xAA by harness).
    cudaMemsetAsync(out, 0, (size_t)out_size * sizeof(float), 0);

    zero_cnt_kernel<<<1, 32>>>();

    {   // t = x @ W + b
        dim3 grid(DMODEL / BN, TOK / BM);
        proj_kernel<<<grid, NTHREADS>>>(x, W, b);
    }

    {   // router (warp per token)
        int warpsPerBlock = NTHREADS / 32;
        int blocks = TOK / warpsPerBlock;
        router_kernel<<<blocks, NTHREADS>>>(Wg, bg);
    }

    for (int e = 0; e < NEXP; e++) {
        dim3 g1(FF / BN, TOK / BM);
        ffn1_kernel<<<g1, NTHREADS>>>(W1, b1, e);
        dim3 g2(DMODEL / BN, TOK / BM);
        ffn2_kernel<<<g2, NTHREADS>>>(W2, b2, out, e);
    }
}

// round 9
// speedup vs baseline: 2.3920x; 2.3920x over previous
#include <cuda_runtime.h>
#include <math.h>

// Problem constants
#define TOK    16384      // 8 * 2048 tokens
#define DMODEL 768
#define NEXP   4
#define FF     1024
#define TOPK   2

// SIMT GEMM tiling (proj)
#define BM 128
#define BN 128
#define BK 8
#define TM 8
#define TN 8
#define NTHREADS 256

// MMA GEMM tiling (FFN)
#define MBM 128
#define MBN 128
#define MBK 16
#define APAD 4     // As stride = MBK + APAD = 20 floats
#define BPAD 8     // Bs stride = MBN + BPAD = 136 floats

// Static device scratch (allocations are forbidden)
__device__ float g_t[TOK * DMODEL];          // post-projection tokens
__device__ float g_hid[TOK * FF];            // per-expert hidden, reused sequentially
__device__ int   g_idx[NEXP * TOK];          // gathered token ids per expert
__device__ float g_gate[NEXP * TOK];         // gate per gathered slot
__device__ int   g_cnt[NEXP];                // tokens per expert

__device__ __forceinline__ float gelu_tanh(float x) {
    float u = 0.7978845608028654f * (x + 0.044715f * x * x * x);
    return 0.5f * x * (1.0f + tanhf(u));
}

__device__ __forceinline__ unsigned f2tf32(float x) {
    unsigned u;
    asm("cvt.rna.tf32.f32 %0, %1;" : "=r"(u) : "f"(x));
    return u;
}

__device__ __forceinline__ void mma_tf32(float* c, const unsigned* a,
                                         unsigned b0, unsigned b1) {
    asm volatile(
        "mma.sync.aligned.m16n8k8.row.col.f32.tf32.tf32.f32 "
        "{%0,%1,%2,%3}, {%4,%5,%6,%7}, {%8,%9}, {%0,%1,%2,%3};"
        : "+f"(c[0]), "+f"(c[1]), "+f"(c[2]), "+f"(c[3])
        : "r"(a[0]), "r"(a[1]), "r"(a[2]), "r"(a[3]), "r"(b0), "r"(b1));
}

// ---------------------------------------------------------------------------
// Kernel 0: reset per-launch state
// ---------------------------------------------------------------------------
__global__ void zero_cnt_kernel() {
    if (threadIdx.x < NEXP) g_cnt[threadIdx.x] = 0;
}

// ---------------------------------------------------------------------------
// Kernel 1: t = input @ W + b   (fp32 SIMT — router precision depends on it)
// ---------------------------------------------------------------------------
__global__ __launch_bounds__(NTHREADS) void proj_kernel(
    const float* __restrict__ A,
    const float* __restrict__ Bm,
    const float* __restrict__ bias)
{
    __shared__ float As[BK][BM];
    __shared__ float Bs[BK][BN];

    const int tid = threadIdx.x;
    const int rowBase = blockIdx.y * BM;
    const int colBase = blockIdx.x * BN;
    const int K = DMODEL, N = DMODEL;

    const int aRow = tid >> 1, aCol = (tid & 1) * 4;
    const int bRow = tid >> 5, bCol = (tid & 31) * 4;
    const int tx = tid & 15, ty = tid >> 4;

    float acc[TM][TN] = {};

    for (int k0 = 0; k0 < K; k0 += BK) {
        float4 av = *(const float4*)&A[(size_t)(rowBase + aRow) * K + k0 + aCol];
        As[aCol + 0][aRow] = av.x;
        As[aCol + 1][aRow] = av.y;
        As[aCol + 2][aRow] = av.z;
        As[aCol + 3][aRow] = av.w;
        *(float4*)&Bs[bRow][bCol] =
            *(const float4*)&Bm[(size_t)(k0 + bRow) * N + colBase + bCol];
        __syncthreads();

        #pragma unroll
        for (int kk = 0; kk < BK; kk++) {
            float a[TM], b[TN];
            #pragma unroll
            for (int i = 0; i < TM; i++) a[i] = As[kk][ty * TM + i];
            #pragma unroll
            for (int j = 0; j < TN; j++) b[j] = Bs[kk][tx * TN + j];
            #pragma unroll
            for (int i = 0; i < TM; i++)
                #pragma unroll
                for (int j = 0; j < TN; j++) acc[i][j] += a[i] * b[j];
        }
        __syncthreads();
    }

    #pragma unroll
    for (int i = 0; i < TM; i++) {
        int r = rowBase + ty * TM + i;
        #pragma unroll
        for (int j = 0; j < TN; j++) {
            int c = colBase + tx * TN + j;
            g_t[(size_t)r * DMODEL + c] = acc[i][j] + bias[c];
        }
    }
}

// ---------------------------------------------------------------------------
// Kernel 2: router — warp per token, top-2, renormalized gates, gather lists
// ---------------------------------------------------------------------------
__global__ void router_kernel(const float* __restrict__ Wg,
                              const float* __restrict__ bg)
{
    int warp = (blockIdx.x * blockDim.x + threadIdx.x) >> 5;
    int lane = threadIdx.x & 31;
    if (warp >= TOK) return;

    const float* row = g_t + (size_t)warp * DMODEL;
    float l0 = 0.f, l1 = 0.f, l2 = 0.f, l3 = 0.f;
    for (int k = lane; k < DMODEL; k += 32) {
        float x = row[k];
        const float* w = Wg + k * NEXP;
        l0 += x * w[0]; l1 += x * w[1]; l2 += x * w[2]; l3 += x * w[3];
    }
    #pragma unroll
    for (int off = 16; off; off >>= 1) {
        l0 += __shfl_xor_sync(0xFFFFFFFFu, l0, off);
        l1 += __shfl_xor_sync(0xFFFFFFFFu, l1, off);
        l2 += __shfl_xor_sync(0xFFFFFFFFu, l2, off);
        l3 += __shfl_xor_sync(0xFFFFFFFFu, l3, off);
    }
    if (lane == 0) {
        float v[NEXP] = { l0 + bg[0], l1 + bg[1], l2 + bg[2], l3 + bg[3] };
        int i1 = 0;
        #pragma unroll
        for (int e = 1; e < NEXP; e++) if (v[e] > v[i1]) i1 = e;
        int i2 = -1;
        #pragma unroll
        for (int e = 0; e < NEXP; e++) {
            if (e == i1) continue;
            if (i2 < 0 || v[e] > v[i2]) i2 = e;
        }
        float gb = expf(v[i2] - v[i1]);
        float s = 1.0f + gb;
        float ga = 1.0f / s;
        gb = gb / s;

        int p1 = atomicAdd(&g_cnt[i1], 1);
        g_idx[i1 * TOK + p1]  = warp;
        g_gate[i1 * TOK + p1] = ga;
        int p2 = atomicAdd(&g_cnt[i2], 1);
        g_idx[i2 * TOK + p2]  = warp;
        g_gate[i2 * TOK + p2] = gb;
    }
}

// ---------------------------------------------------------------------------
// Kernel 3: FFN1 via TF32 mma — hid = gelu(t[gather] @ W1_e + b1_e)
//           M = cnt[e], N = FF, K = DMODEL
// ---------------------------------------------------------------------------
__global__ __launch_bounds__(256, 2) void ffn1_mma_kernel(
    const float* __restrict__ W1,
    const float* __restrict__ b1,
    int e)
{
    const int cnt = g_cnt[e];
    const int rowBase = blockIdx.y * MBM;
    if (rowBase >= cnt) return;

    __shared__ unsigned As[MBM][MBK + APAD];
    __shared__ unsigned Bs[MBK][MBN + BPAD];
    __shared__ int Rows[MBM];

    const int tid = threadIdx.x;
    if (tid < MBM) {
        int r = rowBase + tid;
        Rows[tid] = (r < cnt) ? g_idx[e * TOK + r] : -1;
    }
    __syncthreads();

    const int colBase = blockIdx.x * MBN;
    const float* Bw = W1 + (size_t)e * DMODEL * FF;
    const int N = FF, K = DMODEL;

    // per-thread load slots: A 2x float4, B 2x float4
    int aRowL[2], aC4[2];
    const float* aP[2];
    int bC4[2];
    const float* bP[2];
    #pragma unroll
    for (int i = 0; i < 2; i++) {
        int idx = tid + i * 256;
        aRowL[i] = idx >> 2;
        aC4[i]   = (idx & 3) * 4;
        int tok = Rows[aRowL[i]];
        aP[i] = (tok >= 0) ? g_t + (size_t)tok * DMODEL + aC4[i] : nullptr;

        int brow = idx >> 5;
        bC4[i] = (idx & 31) * 4;
        bP[i] = Bw + (size_t)brow * N + colBase + bC4[i];
        aRowL[i] = aRowL[i];
    }
    int bRowL[2] = { (tid) >> 5, (tid + 256) >> 5 };

    const int wid = tid >> 5, lane = tid & 31;
    const int wm = wid & 1, wn = wid >> 1;       // 2 x 4 warp grid, 64x32 tiles
    const int qr = lane >> 2, qc = lane & 3;

    float acc[4][4][4] = {};
    float4 aReg[2], bReg[2];

    // prologue fetch k0 = 0
    #pragma unroll
    for (int i = 0; i < 2; i++) {
        aReg[i] = aP[i] ? *(const float4*)(aP[i]) : make_float4(0,0,0,0);
        bReg[i] = *(const float4*)(bP[i]);
    }

    for (int k0 = 0; k0 < K; k0 += MBK) {
        // store current tile to smem (tf32 converted)
        #pragma unroll
        for (int i = 0; i < 2; i++) {
            uint4 ua = { f2tf32(aReg[i].x), f2tf32(aReg[i].y),
                         f2tf32(aReg[i].z), f2tf32(aReg[i].w) };
            *(uint4*)&As[(tid + i * 256) >> 2][aC4[i]] = ua;
            uint4 ub = { f2tf32(bReg[i].x), f2tf32(bReg[i].y),
                         f2tf32(bReg[i].z), f2tf32(bReg[i].w) };
            *(uint4*)&Bs[bRowL[i]][bC4[i]] = ub;
        }
        __syncthreads();

        // prefetch next tile
        if (k0 + MBK < K) {
            #pragma unroll
            for (int i = 0; i < 2; i++) {
                aReg[i] = aP[i] ? *(const float4*)(aP[i] + k0 + MBK)
                                : make_float4(0,0,0,0);
                bReg[i] = *(const float4*)(bP[i] + (size_t)(k0 + MBK) * N);
            }
        }

        // compute 2 k-substeps of 8
        #pragma unroll
        for (int ks = 0; ks < MBK; ks += 8) {
            unsigned af[4][4];
            #pragma unroll
            for (int mt = 0; mt < 4; mt++) {
                int r0 = wm * 64 + mt * 16 + qr;
                af[mt][0] = As[r0][ks + qc];
                af[mt][1] = As[r0 + 8][ks + qc];
                af[mt][2] = As[r0][ks + qc + 4];
                af[mt][3] = As[r0 + 8][ks + qc + 4];
            }
            #pragma unroll
            for (int nt = 0; nt < 4; nt++) {
                int c0 = wn * 32 + nt * 8 + qr;
                unsigned b0 = Bs[ks + qc][c0];
                unsigned b1v = Bs[ks + qc + 4][c0];
                #pragma unroll
                for (int mt = 0; mt < 4; mt++)
                    mma_tf32(acc[mt][nt], af[mt], b0, b1v);
            }
        }
        __syncthreads();
    }

    const float* b1e = b1 + (size_t)e * FF;
    #pragma unroll
    for (int mt = 0; mt < 4; mt++) {
        int lr0 = wm * 64 + mt * 16 + qr;
        int r0 = rowBase + lr0, r1 = r0 + 8;
        #pragma unroll
        for (int nt = 0; nt < 4; nt++) {
            int c = colBase + wn * 32 + nt * 8 + qc * 2;
            if (r0 < cnt) {
                g_hid[(size_t)r0 * FF + c]     = gelu_tanh(acc[mt][nt][0] + b1e[c]);
                g_hid[(size_t)r0 * FF + c + 1] = gelu_tanh(acc[mt][nt][1] + b1e[c + 1]);
            }
            if (r1 < cnt) {
                g_hid[(size_t)r1 * FF + c]     = gelu_tanh(acc[mt][nt][2] + b1e[c]);
                g_hid[(size_t)r1 * FF + c + 1] = gelu_tanh(acc[mt][nt][3] + b1e[c + 1]);
            }
        }
    }
}

// ---------------------------------------------------------------------------
// Kernel 4: FFN2 via TF32 mma — out[tok] += gate * (hid @ W2_e + b2_e)
//           M = cnt[e], N = DMODEL, K = FF
// ---------------------------------------------------------------------------
__global__ __launch_bounds__(256, 2) void ffn2_mma_kernel(
    const float* __restrict__ W2,
    const float* __restrict__ b2,
    float* __restrict__ out,
    int e)
{
    const int cnt = g_cnt[e];
    const int rowBase = blockIdx.y * MBM;
    if (rowBase >= cnt) return;

    __shared__ unsigned As[MBM][MBK + APAD];
    __shared__ unsigned Bs[MBK][MBN + BPAD];
    __shared__ int   Rows[MBM];
    __shared__ float Gates[MBM];

    const int tid = threadIdx.x;
    if (tid < MBM) {
        int r = rowBase + tid;
        Rows[tid]  = (r < cnt) ? g_idx[e * TOK + r] : -1;
        Gates[tid] = (r < cnt) ? g_gate[e * TOK + r] : 0.f;
    }
    __syncthreads();

    const int colBase = blockIdx.x * MBN;
    const float* Bw = W2 + (size_t)e * FF * DMODEL;
    const int N = DMODEL, K = FF;

    int aC4[2], bC4[2];
    const float* aP[2];
    const float* bP[2];
    int bRowL[2];
    #pragma unroll
    for (int i = 0; i < 2; i++) {
        int idx = tid + i * 256;
        int arow = idx >> 2;
        aC4[i] = (idx & 3) * 4;
        aP[i] = g_hid + (size_t)(rowBase + arow) * FF + aC4[i];  // dense; stale rows discarded
        bRowL[i] = idx >> 5;
        bC4[i] = (idx & 31) * 4;
        bP[i] = Bw + (size_t)bRowL[i] * N + colBase + bC4[i];
    }

    const int wid = tid >> 5, lane = tid & 31;
    const int wm = wid & 1, wn = wid >> 1;
    const int qr = lane >> 2, qc = lane & 3;

    float acc[4][4][4] = {};
    float4 aReg[2], bReg[2];

    #pragma unroll
    for (int i = 0; i < 2; i++) {
        aReg[i] = *(const float4*)(aP[i]);
        bReg[i] = *(const float4*)(bP[i]);
    }

    for (int k0 = 0; k0 < K; k0 += MBK) {
        #pragma unroll
        for (int i = 0; i < 2; i++) {
            uint4 ua = { f2tf32(aReg[i].x), f2tf32(aReg[i].y),
                         f2tf32(aReg[i].z), f2tf32(aReg[i].w) };
            *(uint4*)&As[(tid + i * 256) >> 2][aC4[i]] = ua;
            uint4 ub = { f2tf32(bReg[i].x), f2tf32(bReg[i].y),
                         f2tf32(bReg[i].z), f2tf32(bReg[i].w) };
            *(uint4*)&Bs[bRowL[i]][bC4[i]] = ub;
        }
        __syncthreads();

        if (k0 + MBK < K) {
            #pragma unroll
            for (int i = 0; i < 2; i++) {
                aReg[i] = *(const float4*)(aP[i] + k0 + MBK);
                bReg[i] = *(const float4*)(bP[i] + (size_t)(k0 + MBK) * N);
            }
        }

        #pragma unroll
        for (int ks = 0; ks < MBK; ks += 8) {
            unsigned af[4][4];
            #pragma unroll
            for (int mt = 0; mt < 4; mt++) {
                int r0 = wm * 64 + mt * 16 + qr;
                af[mt][0] = As[r0][ks + qc];
                af[mt][1] = As[r0 + 8][ks + qc];
                af[mt][2] = As[r0][ks + qc + 4];
                af[mt][3] = As[r0 + 8][ks + qc + 4];
            }
            #pragma unroll
            for (int nt = 0; nt < 4; nt++) {
                int c0 = wn * 32 + nt * 8 + qr;
                unsigned b0 = Bs[ks + qc][c0];
                unsigned b1v = Bs[ks + qc + 4][c0];
                #pragma unroll
                for (int mt = 0; mt < 4; mt++)
                    mma_tf32(acc[mt][nt], af[mt], b0, b1v);
            }
        }
        __syncthreads();
    }

    const float* b2e = b2 + (size_t)e * DMODEL;
    #pragma unroll
    for (int mt = 0; mt < 4; mt++) {
        int lr0 = wm * 64 + mt * 16 + qr;
        int r0 = rowBase + lr0, r1 = r0 + 8;
        int tok0 = Rows[lr0], tok1 = Rows[lr0 + 8];
        float g0 = Gates[lr0], g1 = Gates[lr0 + 8];
        #pragma unroll
        for (int nt = 0; nt < 4; nt++) {
            int c = colBase + wn * 32 + nt * 8 + qc * 2;
            if (r0 < cnt) {
                atomicAdd(&out[(size_t)tok0 * DMODEL + c],
                          g0 * (acc[mt][nt][0] + b2e[c]));
                atomicAdd(&out[(size_t)tok0 * DMODEL + c + 1],
                          g0 * (acc[mt][nt][1] + b2e[c + 1]));
            }
            if (r1 < cnt) {
                atomicAdd(&out[(size_t)tok1 * DMODEL + c],
                          g1 * (acc[mt][nt][2] + b2e[c]));
                atomicAdd(&out[(size_t)tok1 * DMODEL + c + 1],
                          g1 * (acc[mt][nt][3] + b2e[c + 1]));
            }
        }
    }
}

// ---------------------------------------------------------------------------
// Launch — inputs: input_ids, W, b, Wg, bg, W1, b1, W2, b2
// ---------------------------------------------------------------------------
extern "C" void kernel_launch(void* const* d_in, const int* in_sizes, int n_in,
                              void* d_out, int out_size) {
    const float* x   = (const float*)d_in[0];
    const float* W   = (const float*)d_in[1];
    const float* b   = (const float*)d_in[2];
    const float* Wg  = (const float*)d_in[3];
    const float* bg  = (const float*)d_in[4];
    const float* W1  = (const float*)d_in[5];
    const float* b1  = (const float*)d_in[6];
    const float* W2  = (const float*)d_in[7];
    const float* b2  = (const float*)d_in[8];
    float* out = (float*)d_out;

    cudaMemsetAsync(out, 0, (size_t)out_size * sizeof(float), 0);

    zero_cnt_kernel<<<1, 32>>>();

    {   // t = x @ W + b  (fp32)
        dim3 grid(DMODEL / BN, TOK / BM);
        proj_kernel<<<grid, NTHREADS>>>(x, W, b);
    }

    {   // router
        int warpsPerBlock = NTHREADS / 32;
        int blocks = TOK / warpsPerBlock;
        router_kernel<<<blocks, NTHREADS>>>(Wg, bg);
    }

    for (int e = 0; e < NEXP; e++) {
        dim3 g1(FF / MBN, TOK / MBM);
        ffn1_mma_kernel<<<g1, 256>>>(W1, b1, e);
        dim3 g2(DMODEL / MBN, TOK / MBM);
        ffn2_mma_kernel<<<g2, 256>>>(W2, b2, out, e);
    }
}

// round 10
// speedup vs baseline: 2.9572x; 1.2363x over previous
#include <cuda_runtime.h>
#include <math.h>

// Problem constants
#define TOK    16384      // 8 * 2048 tokens
#define DMODEL 768
#define NEXP   4
#define FF     1024

// MMA GEMM tiling (FFN)
#define MBM 128
#define MBN 128
#define MBK 16
#define APAD 4     // As stride = MBK + APAD = 20
#define BPAD 8     // Bs stride = MBN + BPAD = 136

// proj (split-TF32) tiling
#define PBK 8
#define PAPAD 4    // stride 12
#define PBPAD 8    // stride 136

// Static device scratch (allocations forbidden; zero-initialized at load)
__device__ float g_t[(size_t)TOK * DMODEL];          // post-projection tokens
__device__ float g_hid[(size_t)NEXP * TOK * FF];     // per-expert hidden slabs
__device__ int   g_idx[NEXP * TOK];                  // gathered token ids per expert
__device__ float g_gate[NEXP * TOK];                 // gate per gathered slot
__device__ int   g_cnt[NEXP];                        // tokens per expert

__device__ __forceinline__ float gelu_tanh(float x) {
    float u = 0.7978845608028654f * (x + 0.044715f * x * x * x);
    return 0.5f * x * (1.0f + tanhf(u));
}

__device__ __forceinline__ unsigned f2tf32(float x) {
    unsigned u;
    asm("cvt.rna.tf32.f32 %0, %1;" : "=r"(u) : "f"(x));
    return u;
}

__device__ __forceinline__ void mma_tf32(float* c, const unsigned* a,
                                         unsigned b0, unsigned b1) {
    asm volatile(
        "mma.sync.aligned.m16n8k8.row.col.f32.tf32.tf32.f32 "
        "{%0,%1,%2,%3}, {%4,%5,%6,%7}, {%8,%9}, {%0,%1,%2,%3};"
        : "+f"(c[0]), "+f"(c[1]), "+f"(c[2]), "+f"(c[3])
        : "r"(a[0]), "r"(a[1]), "r"(a[2]), "r"(a[3]), "r"(b0), "r"(b1));
}

// ---------------------------------------------------------------------------
// Kernel 0: reset per-launch state
// ---------------------------------------------------------------------------
__global__ void zero_cnt_kernel() {
    if (threadIdx.x < NEXP) g_cnt[threadIdx.x] = 0;
}

// ---------------------------------------------------------------------------
// Kernel 1: t = input @ W + b  via TF32 tensor cores with 3-term split
//           (fp32-equivalent accuracy so the router sees clean logits).
//           a = ah + al, b = bh + bl (tf32 RNA splits, ah exact in fp32);
//           acc += ah*bh + al*bh + ah*bl  (al*bl ~ 2^-22, dropped)
// ---------------------------------------------------------------------------
__global__ __launch_bounds__(256, 2) void proj_mma_kernel(
    const float* __restrict__ A,     // [TOK, DMODEL]
    const float* __restrict__ Wm,    // [DMODEL, DMODEL]
    const float* __restrict__ bias)  // [DMODEL]
{
    __shared__ unsigned Ash[2][MBM][PBK + PAPAD];
    __shared__ unsigned Asl[2][MBM][PBK + PAPAD];
    __shared__ unsigned Bsh[2][PBK][MBN + PBPAD];
    __shared__ unsigned Bsl[2][PBK][MBN + PBPAD];

    const int tid = threadIdx.x;
    const int rowBase = blockIdx.y * MBM;
    const int colBase = blockIdx.x * MBN;
    const int K = DMODEL, N = DMODEL;

    const int aRow = tid >> 1, aC4 = (tid & 1) * 4;
    const int bRow = tid >> 5, bC4 = (tid & 31) * 4;
    const float* aP = A + (size_t)(rowBase + aRow) * K + aC4;
    const float* bP = Wm + (size_t)bRow * N + colBase + bC4;

    const int wid = tid >> 5, lane = tid & 31;
    const int wm = wid & 1, wn = wid >> 1;   // 2x4 warp grid, 64x32 tiles
    const int qr = lane >> 2, qc = lane & 3;

    float acc[4][4][4] = {};
    float4 aReg = *(const float4*)aP;
    float4 bReg = *(const float4*)bP;

#define PROJ_STORE(BUFI)                                                      \
    {                                                                         \
        uint4 ah, al, bh, bl;                                                 \
        ah.x = f2tf32(aReg.x); al.x = f2tf32(aReg.x - __uint_as_float(ah.x)); \
        ah.y = f2tf32(aReg.y); al.y = f2tf32(aReg.y - __uint_as_float(ah.y)); \
        ah.z = f2tf32(aReg.z); al.z = f2tf32(aReg.z - __uint_as_float(ah.z)); \
        ah.w = f2tf32(aReg.w); al.w = f2tf32(aReg.w - __uint_as_float(ah.w)); \
        *(uint4*)&Ash[BUFI][aRow][aC4] = ah;                                  \
        *(uint4*)&Asl[BUFI][aRow][aC4] = al;                                  \
        bh.x = f2tf32(bReg.x); bl.x = f2tf32(bReg.x - __uint_as_float(bh.x)); \
        bh.y = f2tf32(bReg.y); bl.y = f2tf32(bReg.y - __uint_as_float(bh.y)); \
        bh.z = f2tf32(bReg.z); bl.z = f2tf32(bReg.z - __uint_as_float(bh.z)); \
        bh.w = f2tf32(bReg.w); bl.w = f2tf32(bReg.w - __uint_as_float(bh.w)); \
        *(uint4*)&Bsh[BUFI][bRow][bC4] = bh;                                  \
        *(uint4*)&Bsl[BUFI][bRow][bC4] = bl;                                  \
    }

    PROJ_STORE(0);
    __syncthreads();

    int buf = 0;
    for (int k0 = 0; k0 < K; k0 += PBK) {
        const bool nxt = (k0 + PBK) < K;
        if (nxt) {
            aReg = *(const float4*)(aP + k0 + PBK);
            bReg = *(const float4*)(bP + (size_t)(k0 + PBK) * N);
        }

        unsigned ahi[4][4], alo[4][4];
        #pragma unroll
        for (int mt = 0; mt < 4; mt++) {
            int r0 = wm * 64 + mt * 16 + qr;
            ahi[mt][0] = Ash[buf][r0][qc];     ahi[mt][1] = Ash[buf][r0 + 8][qc];
            ahi[mt][2] = Ash[buf][r0][qc + 4]; ahi[mt][3] = Ash[buf][r0 + 8][qc + 4];
            alo[mt][0] = Asl[buf][r0][qc];     alo[mt][1] = Asl[buf][r0 + 8][qc];
            alo[mt][2] = Asl[buf][r0][qc + 4]; alo[mt][3] = Asl[buf][r0 + 8][qc + 4];
        }
        #pragma unroll
        for (int nt = 0; nt < 4; nt++) {
            int c0 = wn * 32 + nt * 8 + qr;
            unsigned bh0 = Bsh[buf][qc][c0], bh1 = Bsh[buf][qc + 4][c0];
            unsigned bl0 = Bsl[buf][qc][c0], bl1 = Bsl[buf][qc + 4][c0];
            #pragma unroll
            for (int mt = 0; mt < 4; mt++) {
                mma_tf32(acc[mt][nt], ahi[mt], bh0, bh1);
                mma_tf32(acc[mt][nt], alo[mt], bh0, bh1);
                mma_tf32(acc[mt][nt], ahi[mt], bl0, bl1);
            }
        }

        if (nxt) PROJ_STORE(buf ^ 1);
        __syncthreads();
        buf ^= 1;
    }
#undef PROJ_STORE

    #pragma unroll
    for (int mt = 0; mt < 4; mt++) {
        int r0 = rowBase + wm * 64 + mt * 16 + qr;
        int r1 = r0 + 8;
        #pragma unroll
        for (int nt = 0; nt < 4; nt++) {
            int c = colBase + wn * 32 + nt * 8 + qc * 2;
            float2 o0 = { acc[mt][nt][0] + bias[c], acc[mt][nt][1] + bias[c + 1] };
            *(float2*)&g_t[(size_t)r0 * DMODEL + c] = o0;
            float2 o1 = { acc[mt][nt][2] + bias[c], acc[mt][nt][3] + bias[c + 1] };
            *(float2*)&g_t[(size_t)r1 * DMODEL + c] = o1;
        }
    }
}

// ---------------------------------------------------------------------------
// Kernel 2: router — warp per token, top-2, renormalized gates, gather lists
// ---------------------------------------------------------------------------
__global__ void router_kernel(const float* __restrict__ Wg,
                              const float* __restrict__ bg)
{
    int warp = (blockIdx.x * blockDim.x + threadIdx.x) >> 5;
    int lane = threadIdx.x & 31;
    if (warp >= TOK) return;

    const float* row = g_t + (size_t)warp * DMODEL;
    float l0 = 0.f, l1 = 0.f, l2 = 0.f, l3 = 0.f;
    for (int k = lane; k < DMODEL; k += 32) {
        float x = row[k];
        const float* w = Wg + k * NEXP;
        l0 += x * w[0]; l1 += x * w[1]; l2 += x * w[2]; l3 += x * w[3];
    }
    #pragma unroll
    for (int off = 16; off; off >>= 1) {
        l0 += __shfl_xor_sync(0xFFFFFFFFu, l0, off);
        l1 += __shfl_xor_sync(0xFFFFFFFFu, l1, off);
        l2 += __shfl_xor_sync(0xFFFFFFFFu, l2, off);
        l3 += __shfl_xor_sync(0xFFFFFFFFu, l3, off);
    }
    if (lane == 0) {
        float v[NEXP] = { l0 + bg[0], l1 + bg[1], l2 + bg[2], l3 + bg[3] };
        int i1 = 0;
        #pragma unroll
        for (int e = 1; e < NEXP; e++) if (v[e] > v[i1]) i1 = e;
        int i2 = -1;
        #pragma unroll
        for (int e = 0; e < NEXP; e++) {
            if (e == i1) continue;
            if (i2 < 0 || v[e] > v[i2]) i2 = e;
        }
        float gb = expf(v[i2] - v[i1]);
        float s = 1.0f + gb;
        float ga = 1.0f / s;
        gb = gb / s;

        int p1 = atomicAdd(&g_cnt[i1], 1);
        g_idx[i1 * TOK + p1]  = warp;
        g_gate[i1 * TOK + p1] = ga;
        int p2 = atomicAdd(&g_cnt[i2], 1);
        g_idx[i2 * TOK + p2]  = warp;
        g_gate[i2 * TOK + p2] = gb;
    }
}

// ---------------------------------------------------------------------------
// Kernel 3: FFN1 (all experts fused; blockIdx.z = expert), TF32 mma,
//           double-buffered smem: hid_e = gelu(t[gather_e] @ W1_e + b1_e)
// ---------------------------------------------------------------------------
__global__ __launch_bounds__(256, 2) void ffn1_mma_kernel(
    const float* __restrict__ W1,   // [NEXP, DMODEL, FF]
    const float* __restrict__ b1)   // [NEXP, FF]
{
    const int e = blockIdx.z;
    const int cnt = g_cnt[e];
    const int rowBase = blockIdx.y * MBM;
    if (rowBase >= cnt) return;

    __shared__ unsigned As[2][MBM][MBK + APAD];
    __shared__ unsigned Bs[2][MBK][MBN + BPAD];
    __shared__ int Rows[MBM];

    const int tid = threadIdx.x;
    if (tid < MBM) {
        int r = rowBase + tid;
        Rows[tid] = (r < cnt) ? g_idx[e * TOK + r] : -1;
    }
    __syncthreads();

    const int colBase = blockIdx.x * MBN;
    const float* Bw = W1 + (size_t)e * DMODEL * FF;
    const int N = FF, K = DMODEL;

    int aRowL[2], aC4[2], bRowL[2], bC4[2];
    const float* aP[2];
    const float* bP[2];
    #pragma unroll
    for (int i = 0; i < 2; i++) {
        int idx = tid + i * 256;
        aRowL[i] = idx >> 2;
        aC4[i]   = (idx & 3) * 4;
        int tok = Rows[aRowL[i]];
        aP[i] = (tok >= 0) ? g_t + (size_t)tok * DMODEL + aC4[i] : nullptr;
        bRowL[i] = idx >> 5;
        bC4[i]   = (idx & 31) * 4;
        bP[i] = Bw + (size_t)bRowL[i] * N + colBase + bC4[i];
    }

    const int wid = tid >> 5, lane = tid & 31;
    const int wm = wid & 1, wn = wid >> 1;
    const int qr = lane >> 2, qc = lane & 3;

    float acc[4][4][4] = {};
    float4 aReg[2], bReg[2];
    #pragma unroll
    for (int i = 0; i < 2; i++) {
        aReg[i] = aP[i] ? *(const float4*)aP[i] : make_float4(0, 0, 0, 0);
        bReg[i] = *(const float4*)bP[i];
    }

#define FFN_STORE(BUFI)                                                        \
    _Pragma("unroll")                                                          \
    for (int i = 0; i < 2; i++) {                                              \
        uint4 ua = { f2tf32(aReg[i].x), f2tf32(aReg[i].y),                     \
                     f2tf32(aReg[i].z), f2tf32(aReg[i].w) };                   \
        *(uint4*)&As[BUFI][aRowL[i]][aC4[i]] = ua;                             \
        uint4 ub = { f2tf32(bReg[i].x), f2tf32(bReg[i].y),                     \
                     f2tf32(bReg[i].z), f2tf32(bReg[i].w) };                   \
        *(uint4*)&Bs[BUFI][bRowL[i]][bC4[i]] = ub;                             \
    }

    FFN_STORE(0);
    __syncthreads();

    int buf = 0;
    for (int k0 = 0; k0 < K; k0 += MBK) {
        const bool nxt = (k0 + MBK) < K;
        if (nxt) {
            #pragma unroll
            for (int i = 0; i < 2; i++) {
                aReg[i] = aP[i] ? *(const float4*)(aP[i] + k0 + MBK)
                                : make_float4(0, 0, 0, 0);
                bReg[i] = *(const float4*)(bP[i] + (size_t)(k0 + MBK) * N);
            }
        }

        #pragma unroll
        for (int ks = 0; ks < MBK; ks += 8) {
            unsigned af[4][4];
            #pragma unroll
            for (int mt = 0; mt < 4; mt++) {
                int r0 = wm * 64 + mt * 16 + qr;
                af[mt][0] = As[buf][r0][ks + qc];
                af[mt][1] = As[buf][r0 + 8][ks + qc];
                af[mt][2] = As[buf][r0][ks + qc + 4];
                af[mt][3] = As[buf][r0 + 8][ks + qc + 4];
            }
            #pragma unroll
            for (int nt = 0; nt < 4; nt++) {
                int c0 = wn * 32 + nt * 8 + qr;
                unsigned b0 = Bs[buf][ks + qc][c0];
                unsigned b1v = Bs[buf][ks + qc + 4][c0];
                #pragma unroll
                for (int mt = 0; mt < 4; mt++)
                    mma_tf32(acc[mt][nt], af[mt], b0, b1v);
            }
        }

        if (nxt) FFN_STORE(buf ^ 1);
        __syncthreads();
        buf ^= 1;
    }

    const float* b1e = b1 + (size_t)e * FF;
    float* hidE = g_hid + (size_t)e * TOK * FF;
    #pragma unroll
    for (int mt = 0; mt < 4; mt++) {
        int lr0 = wm * 64 + mt * 16 + qr;
        int r0 = rowBase + lr0, r1 = r0 + 8;
        #pragma unroll
        for (int nt = 0; nt < 4; nt++) {
            int c = colBase + wn * 32 + nt * 8 + qc * 2;
            if (r0 < cnt) {
                float2 o = { gelu_tanh(acc[mt][nt][0] + b1e[c]),
                             gelu_tanh(acc[mt][nt][1] + b1e[c + 1]) };
                *(float2*)&hidE[(size_t)r0 * FF + c] = o;
            }
            if (r1 < cnt) {
                float2 o = { gelu_tanh(acc[mt][nt][2] + b1e[c]),
                             gelu_tanh(acc[mt][nt][3] + b1e[c + 1]) };
                *(float2*)&hidE[(size_t)r1 * FF + c] = o;
            }
        }
    }
}

// ---------------------------------------------------------------------------
// Kernel 4: FFN2 (all experts fused; blockIdx.z = expert), TF32 mma,
//           double-buffered smem: out[tok] += gate * (hid_e @ W2_e + b2_e)
// ---------------------------------------------------------------------------
__global__ __launch_bounds__(256, 2) void ffn2_mma_kernel(
    const float* __restrict__ W2,   // [NEXP, FF, DMODEL]
    const float* __restrict__ b2,   // [NEXP, DMODEL]
    float* __restrict__ out)        // [TOK, DMODEL], pre-zeroed
{
    const int e = blockIdx.z;
    const int cnt = g_cnt[e];
    const int rowBase = blockIdx.y * MBM;
    if (rowBase >= cnt) return;

    __shared__ unsigned As[2][MBM][MBK + APAD];
    __shared__ unsigned Bs[2][MBK][MBN + BPAD];
    __shared__ int   Rows[MBM];
    __shared__ float Gates[MBM];

    const int tid = threadIdx.x;
    if (tid < MBM) {
        int r = rowBase + tid;
        Rows[tid]  = (r < cnt) ? g_idx[e * TOK + r] : -1;
        Gates[tid] = (r < cnt) ? g_gate[e * TOK + r] : 0.f;
    }
    __syncthreads();

    const int colBase = blockIdx.x * MBN;
    const float* Bw = W2 + (size_t)e * FF * DMODEL;
    const float* hidE = g_hid + (size_t)e * TOK * FF;
    const int N = DMODEL, K = FF;

    int aRowL[2], aC4[2], bRowL[2], bC4[2];
    const float* aP[2];
    const float* bP[2];
    #pragma unroll
    for (int i = 0; i < 2; i++) {
        int idx = tid + i * 256;
        aRowL[i] = idx >> 2;
        aC4[i]   = (idx & 3) * 4;
        aP[i] = hidE + (size_t)(rowBase + aRowL[i]) * FF + aC4[i];  // dense; stale rows discarded
        bRowL[i] = idx >> 5;
        bC4[i]   = (idx & 31) * 4;
        bP[i] = Bw + (size_t)bRowL[i] * N + colBase + bC4[i];
    }

    const int wid = tid >> 5, lane = tid & 31;
    const int wm = wid & 1, wn = wid >> 1;
    const int qr = lane >> 2, qc = lane & 3;

    float acc[4][4][4] = {};
    float4 aReg[2], bReg[2];
    #pragma unroll
    for (int i = 0; i < 2; i++) {
        aReg[i] = *(const float4*)aP[i];
        bReg[i] = *(const float4*)bP[i];
    }

    FFN_STORE(0);
    __syncthreads();

    int buf = 0;
    for (int k0 = 0; k0 < K; k0 += MBK) {
        const bool nxt = (k0 + MBK) < K;
        if (nxt) {
            #pragma unroll
            for (int i = 0; i < 2; i++) {
                aReg[i] = *(const float4*)(aP[i] + k0 + MBK);
                bReg[i] = *(const float4*)(bP[i] + (size_t)(k0 + MBK) * N);
            }
        }

        #pragma unroll
        for (int ks = 0; ks < MBK; ks += 8) {
            unsigned af[4][4];
            #pragma unroll
            for (int mt = 0; mt < 4; mt++) {
                int r0 = wm * 64 + mt * 16 + qr;
                af[mt][0] = As[buf][r0][ks + qc];
                af[mt][1] = As[buf][r0 + 8][ks + qc];
                af[mt][2] = As[buf][r0][ks + qc + 4];
                af[mt][3] = As[buf][r0 + 8][ks + qc + 4];
            }
            #pragma unroll
            for (int nt = 0; nt < 4; nt++) {
                int c0 = wn * 32 + nt * 8 + qr;
                unsigned b0 = Bs[buf][ks + qc][c0];
                unsigned b1v = Bs[buf][ks + qc + 4][c0];
                #pragma unroll
                for (int mt = 0; mt < 4; mt++)
                    mma_tf32(acc[mt][nt], af[mt], b0, b1v);
            }
        }

        if (nxt) FFN_STORE(buf ^ 1);
        __syncthreads();
        buf ^= 1;
    }

    const float* b2e = b2 + (size_t)e * DMODEL;
    #pragma unroll
    for (int mt = 0; mt < 4; mt++) {
        int lr0 = wm * 64 + mt * 16 + qr;
        int r0 = rowBase + lr0, r1 = r0 + 8;
        int tok0 = Rows[lr0], tok1 = Rows[lr0 + 8];
        float g0 = Gates[lr0], g1 = Gates[lr0 + 8];
        #pragma unroll
        for (int nt = 0; nt < 4; nt++) {
            int c = colBase + wn * 32 + nt * 8 + qc * 2;
            if (r0 < cnt) {
                atomicAdd(&out[(size_t)tok0 * DMODEL + c],
                          g0 * (acc[mt][nt][0] + b2e[c]));
                atomicAdd(&out[(size_t)tok0 * DMODEL + c + 1],
                          g0 * (acc[mt][nt][1] + b2e[c + 1]));
            }
            if (r1 < cnt) {
                atomicAdd(&out[(size_t)tok1 * DMODEL + c],
                          g1 * (acc[mt][nt][2] + b2e[c]));
                atomicAdd(&out[(size_t)tok1 * DMODEL + c + 1],
                          g1 * (acc[mt][nt][3] + b2e[c + 1]));
            }
        }
    }
}
#undef FFN_STORE

// ---------------------------------------------------------------------------
// Launch — inputs: input_ids, W, b, Wg, bg, W1, b1, W2, b2
// ---------------------------------------------------------------------------
extern "C" void kernel_launch(void* const* d_in, const int* in_sizes, int n_in,
                              void* d_out, int out_size) {
    const float* x   = (const float*)d_in[0];
    const float* W   = (const float*)d_in[1];
    const float* b   = (const float*)d_in[2];
    const float* Wg  = (const float*)d_in[3];
    const float* bg  = (const float*)d_in[4];
    const float* W1  = (const float*)d_in[5];
    const float* b1  = (const float*)d_in[6];
    const float* W2  = (const float*)d_in[7];
    const float* b2  = (const float*)d_in[8];
    float* out = (float*)d_out;

    cudaMemsetAsync(out, 0, (size_t)out_size * sizeof(float), 0);

    zero_cnt_kernel<<<1, 32>>>();

    {   // t = x @ W + b  (split-TF32 tensor cores, fp32-equivalent)
        dim3 grid(DMODEL / MBN, TOK / MBM);
        proj_mma_kernel<<<grid, 256>>>(x, W, b);
    }

    {   // router
        int warpsPerBlock = 256 / 32;
        int blocks = TOK / warpsPerBlock;
        router_kernel<<<blocks, 256>>>(Wg, bg);
    }

    {   // FFN1: all experts in one launch
        dim3 g1(FF / MBN, TOK / MBM, NEXP);
        ffn1_mma_kernel<<<g1, 256>>>(W1, b1);
    }
    {   // FFN2: all experts in one launch
        dim3 g2(DMODEL / MBN, TOK / MBM, NEXP);
        ffn2_mma_kernel<<<g2, 256>>>(W2, b2, out);
    }
}

// round 14
// speedup vs baseline: 3.2495x; 1.0988x over previous
#include <cuda_runtime.h>
#include <cstdint>
#include <math.h>

// Problem constants
#define TOK    16384      // 8 * 2048 tokens
#define DMODEL 768
#define NEXP   4
#define FF     1024

// MMA GEMM tiling (FFN, cp.async pipeline)
#define MBM 128
#define MBN 128
#define MBK 16
#define STAGES 4
#define ASTRIDE 20                 // floats per A row in smem (conflict-free)
#define BSTRIDE 136                // floats per B row in smem (conflict-free)
#define A_STAGE_FLOATS (MBM * ASTRIDE)      // 2560
#define B_STAGE_FLOATS (MBK * BSTRIDE)      // 2176
#define SMEM_BYTES ((STAGES * (A_STAGE_FLOATS + B_STAGE_FLOATS)) * 4)  // 75776

// proj (split-TF32) tiling
#define PBK 8
#define PAPAD 4
#define PBPAD 8

// Static device scratch (allocations forbidden; zero-initialized at load)
__device__ float g_t[(size_t)TOK * DMODEL];          // post-projection tokens
__device__ float g_hid[(size_t)NEXP * TOK * FF];     // per-expert hidden slabs
__device__ int   g_idx[NEXP * TOK];                  // gathered token ids per expert
__device__ float g_gate[NEXP * TOK];                 // gate per gathered slot
__device__ int   g_cnt[NEXP];                        // tokens per expert

__device__ __forceinline__ float gelu_tanh(float x) {
    float u = 0.7978845608028654f * (x + 0.044715f * x * x * x);
    return 0.5f * x * (1.0f + tanhf(u));
}

__device__ __forceinline__ unsigned f2tf32(float x) {
    unsigned u;
    asm("cvt.rna.tf32.f32 %0, %1;" : "=r"(u) : "f"(x));
    return u;
}

__device__ __forceinline__ void mma_tf32(float* c, const unsigned* a,
                                         unsigned b0, unsigned b1) {
    asm volatile(
        "mma.sync.aligned.m16n8k8.row.col.f32.tf32.tf32.f32 "
        "{%0,%1,%2,%3}, {%4,%5,%6,%7}, {%8,%9}, {%0,%1,%2,%3};"
        : "+f"(c[0]), "+f"(c[1]), "+f"(c[2]), "+f"(c[3])
        : "r"(a[0]), "r"(a[1]), "r"(a[2]), "r"(a[3]), "r"(b0), "r"(b1));
}

__device__ __forceinline__ void cp_async16(uint32_t saddr, const void* gptr) {
    asm volatile("cp.async.cg.shared.global [%0], [%1], 16;"
                 :: "r"(saddr), "l"(gptr));
}
__device__ __forceinline__ void cp_commit() {
    asm volatile("cp.async.commit_group;");
}
__device__ __forceinline__ void cp_wait2() {
    asm volatile("cp.async.wait_group 2;");
}

// ---------------------------------------------------------------------------
// FFN pipeline helpers
// ---------------------------------------------------------------------------
struct PipeCtx {
    uint32_t sA[STAGES];
    uint32_t sB[STAGES];
    uint32_t aOff0, aOff1, bOff0, bOff1;
    const float* aSrc0;
    const float* aSrc1;
    const float* bSrc0;
    const float* bSrc1;
    int GN;                      // B gmem row stride
};

__device__ __forceinline__ void issue_stage(const PipeCtx& c, int slot, int kt) {
    cp_async16(c.sA[slot] + c.aOff0, c.aSrc0 + (size_t)kt * MBK);
    cp_async16(c.sA[slot] + c.aOff1, c.aSrc1 + (size_t)kt * MBK);
    cp_async16(c.sB[slot] + c.bOff0, c.bSrc0 + (size_t)kt * MBK * c.GN);
    cp_async16(c.sB[slot] + c.bOff1, c.bSrc1 + (size_t)kt * MBK * c.GN);
}

__device__ __forceinline__ void compute_stage(const float* __restrict__ smA,
                                              const float* __restrict__ smB,
                                              int wm, int wn, int qr, int qc,
                                              float (&acc)[4][4][4]) {
    #pragma unroll
    for (int ks = 0; ks < MBK; ks += 8) {
        unsigned af[4][4];
        #pragma unroll
        for (int mt = 0; mt < 4; mt++) {
            int r0 = wm * 64 + mt * 16 + qr;
            af[mt][0] = f2tf32(smA[r0 * ASTRIDE + ks + qc]);
            af[mt][1] = f2tf32(smA[(r0 + 8) * ASTRIDE + ks + qc]);
            af[mt][2] = f2tf32(smA[r0 * ASTRIDE + ks + qc + 4]);
            af[mt][3] = f2tf32(smA[(r0 + 8) * ASTRIDE + ks + qc + 4]);
        }
        #pragma unroll
        for (int nt = 0; nt < 4; nt++) {
            int c0 = wn * 32 + nt * 8 + qr;
            unsigned b0  = f2tf32(smB[(ks + qc) * BSTRIDE + c0]);
            unsigned b1v = f2tf32(smB[(ks + qc + 4) * BSTRIDE + c0]);
            #pragma unroll
            for (int mt = 0; mt < 4; mt++)
                mma_tf32(acc[mt][nt], af[mt], b0, b1v);
        }
    }
}

// Runs the full K loop (NT tiles, NT % STAGES == 0) over the pipeline.
__device__ __forceinline__ void run_pipeline(const PipeCtx& c,
                                             const float* __restrict__ smem,
                                             int NT, int wm, int wn,
                                             int qr, int qc,
                                             float (&acc)[4][4][4]) {
    #pragma unroll
    for (int s = 0; s < STAGES - 1; s++) {
        issue_stage(c, s, s);
        cp_commit();
    }
    for (int base = 0; base < NT; base += STAGES) {
        #pragma unroll
        for (int s = 0; s < STAGES; s++) {
            const int ktc = base + s;
            cp_wait2();
            __syncthreads();
            const int kp = ktc + STAGES - 1;
            if (kp < NT) issue_stage(c, (s + STAGES - 1) % STAGES, kp);
            cp_commit();
            const float* smA = smem + s * A_STAGE_FLOATS;
            const float* smB = smem + STAGES * A_STAGE_FLOATS + s * B_STAGE_FLOATS;
            compute_stage(smA, smB, wm, wn, qr, qc, acc);
        }
    }
}

__device__ __forceinline__ void init_ctx_smem(PipeCtx& c, const float* smem) {
    uint32_t smemBase = (uint32_t)__cvta_generic_to_shared(smem);
    #pragma unroll
    for (int s = 0; s < STAGES; s++) {
        c.sA[s] = smemBase + s * A_STAGE_FLOATS * 4;
        c.sB[s] = smemBase + (STAGES * A_STAGE_FLOATS + s * B_STAGE_FLOATS) * 4;
    }
}

// ---------------------------------------------------------------------------
// Kernel 0: reset per-launch state
// ---------------------------------------------------------------------------
__global__ void zero_cnt_kernel() {
    if (threadIdx.x < NEXP) g_cnt[threadIdx.x] = 0;
}

// ---------------------------------------------------------------------------
// Kernel 1: t = input @ W + b  (split-TF32 tensor cores, fp32-equivalent;
//           router precision depends on it)
// ---------------------------------------------------------------------------
__global__ __launch_bounds__(256, 2) void proj_mma_kernel(
    const float* __restrict__ A,
    const float* __restrict__ Wm,
    const float* __restrict__ bias)
{
    __shared__ unsigned Ash[2][MBM][PBK + PAPAD];
    __shared__ unsigned Asl[2][MBM][PBK + PAPAD];
    __shared__ unsigned Bsh[2][PBK][MBN + PBPAD];
    __shared__ unsigned Bsl[2][PBK][MBN + PBPAD];

    const int tid = threadIdx.x;
    const int rowBase = blockIdx.y * MBM;
    const int colBase = blockIdx.x * MBN;
    const int K = DMODEL, N = DMODEL;

    const int aRow = tid >> 1, aC4 = (tid & 1) * 4;
    const int bRow = tid >> 5, bC4 = (tid & 31) * 4;
    const float* aP = A + (size_t)(rowBase + aRow) * K + aC4;
    const float* bP = Wm + (size_t)bRow * N + colBase + bC4;

    const int wid = tid >> 5, lane = tid & 31;
    const int wm = wid & 1, wn = wid >> 1;
    const int qr = lane >> 2, qc = lane & 3;

    float acc[4][4][4] = {};
    float4 aReg = *(const float4*)aP;
    float4 bReg = *(const float4*)bP;

    auto proj_store = [&](int bi) {
        uint4 ah, al, bh, bl;
        ah.x = f2tf32(aReg.x); al.x = f2tf32(aReg.x - __uint_as_float(ah.x));
        ah.y = f2tf32(aReg.y); al.y = f2tf32(aReg.y - __uint_as_float(ah.y));
        ah.z = f2tf32(aReg.z); al.z = f2tf32(aReg.z - __uint_as_float(ah.z));
        ah.w = f2tf32(aReg.w); al.w = f2tf32(aReg.w - __uint_as_float(ah.w));
        *(uint4*)&Ash[bi][aRow][aC4] = ah;
        *(uint4*)&Asl[bi][aRow][aC4] = al;
        bh.x = f2tf32(bReg.x); bl.x = f2tf32(bReg.x - __uint_as_float(bh.x));
        bh.y = f2tf32(bReg.y); bl.y = f2tf32(bReg.y - __uint_as_float(bh.y));
        bh.z = f2tf32(bReg.z); bl.z = f2tf32(bReg.z - __uint_as_float(bh.z));
        bh.w = f2tf32(bReg.w); bl.w = f2tf32(bReg.w - __uint_as_float(bh.w));
        *(uint4*)&Bsh[bi][bRow][bC4] = bh;
        *(uint4*)&Bsl[bi][bRow][bC4] = bl;
    };

    proj_store(0);
    __syncthreads();

    int buf = 0;
    for (int k0 = 0; k0 < K; k0 += PBK) {
        const bool nxt = (k0 + PBK) < K;
        if (nxt) {
            aReg = *(const float4*)(aP + k0 + PBK);
            bReg = *(const float4*)(bP + (size_t)(k0 + PBK) * N);
        }

        unsigned ahi[4][4], alo[4][4];
        #pragma unroll
        for (int mt = 0; mt < 4; mt++) {
            int r0 = wm * 64 + mt * 16 + qr;
            ahi[mt][0] = Ash[buf][r0][qc];     ahi[mt][1] = Ash[buf][r0 + 8][qc];
            ahi[mt][2] = Ash[buf][r0][qc + 4]; ahi[mt][3] = Ash[buf][r0 + 8][qc + 4];
            alo[mt][0] = Asl[buf][r0][qc];     alo[mt][1] = Asl[buf][r0 + 8][qc];
            alo[mt][2] = Asl[buf][r0][qc + 4]; alo[mt][3] = Asl[buf][r0 + 8][qc + 4];
        }
        #pragma unroll
        for (int nt = 0; nt < 4; nt++) {
            int c0 = wn * 32 + nt * 8 + qr;
            unsigned bh0 = Bsh[buf][qc][c0], bh1 = Bsh[buf][qc + 4][c0];
            unsigned bl0 = Bsl[buf][qc][c0], bl1 = Bsl[buf][qc + 4][c0];
            #pragma unroll
            for (int mt = 0; mt < 4; mt++) {
                mma_tf32(acc[mt][nt], ahi[mt], bh0, bh1);
                mma_tf32(acc[mt][nt], alo[mt], bh0, bh1);
                mma_tf32(acc[mt][nt], ahi[mt], bl0, bl1);
            }
        }

        if (nxt) proj_store(buf ^ 1);
        __syncthreads();
        buf ^= 1;
    }

    #pragma unroll
    for (int mt = 0; mt < 4; mt++) {
        int r0 = rowBase + wm * 64 + mt * 16 + qr;
        int r1 = r0 + 8;
        #pragma unroll
        for (int nt = 0; nt < 4; nt++) {
            int c = colBase + wn * 32 + nt * 8 + qc * 2;
            float2 o0 = { acc[mt][nt][0] + bias[c], acc[mt][nt][1] + bias[c + 1] };
            *(float2*)&g_t[(size_t)r0 * DMODEL + c] = o0;
            float2 o1 = { acc[mt][nt][2] + bias[c], acc[mt][nt][3] + bias[c + 1] };
            *(float2*)&g_t[(size_t)r1 * DMODEL + c] = o1;
        }
    }
}

// ---------------------------------------------------------------------------
// Kernel 2: router — warp per token, top-2, renormalized gates, gather lists
// ---------------------------------------------------------------------------
__global__ void router_kernel(const float* __restrict__ Wg,
                              const float* __restrict__ bg)
{
    int warp = (blockIdx.x * blockDim.x + threadIdx.x) >> 5;
    int lane = threadIdx.x & 31;
    if (warp >= TOK) return;

    const float* row = g_t + (size_t)warp * DMODEL;
    float l0 = 0.f, l1 = 0.f, l2 = 0.f, l3 = 0.f;
    for (int k = lane; k < DMODEL; k += 32) {
        float x = row[k];
        const float* w = Wg + k * NEXP;
        l0 += x * w[0]; l1 += x * w[1]; l2 += x * w[2]; l3 += x * w[3];
    }
    #pragma unroll
    for (int off = 16; off; off >>= 1) {
        l0 += __shfl_xor_sync(0xFFFFFFFFu, l0, off);
        l1 += __shfl_xor_sync(0xFFFFFFFFu, l1, off);
        l2 += __shfl_xor_sync(0xFFFFFFFFu, l2, off);
        l3 += __shfl_xor_sync(0xFFFFFFFFu, l3, off);
    }
    if (lane == 0) {
        float v[NEXP] = { l0 + bg[0], l1 + bg[1], l2 + bg[2], l3 + bg[3] };
        int i1 = 0;
        #pragma unroll
        for (int e = 1; e < NEXP; e++) if (v[e] > v[i1]) i1 = e;
        int i2 = -1;
        #pragma unroll
        for (int e = 0; e < NEXP; e++) {
            if (e == i1) continue;
            if (i2 < 0 || v[e] > v[i2]) i2 = e;
        }
        float gb = expf(v[i2] - v[i1]);
        float s = 1.0f + gb;
        float ga = 1.0f / s;
        gb = gb / s;

        int p1 = atomicAdd(&g_cnt[i1], 1);
        g_idx[i1 * TOK + p1]  = warp;
        g_gate[i1 * TOK + p1] = ga;
        int p2 = atomicAdd(&g_cnt[i2], 1);
        g_idx[i2 * TOK + p2]  = warp;
        g_gate[i2 * TOK + p2] = gb;
    }
}

// ---------------------------------------------------------------------------
// Kernel 3: FFN1 — 4-stage cp.async pipeline, TF32 mma.
//           hid_e = gelu(t[gather_e] @ W1_e + b1_e); K=DMODEL(768), N=FF
// ---------------------------------------------------------------------------
__global__ __launch_bounds__(256, 2) void ffn1_mma_kernel(
    const float* __restrict__ W1,
    const float* __restrict__ b1)
{
    const int e = blockIdx.z;
    const int cnt = g_cnt[e];
    const int rowBase = blockIdx.y * MBM;
    if (rowBase >= cnt) return;

    extern __shared__ float smem[];
    __shared__ int Rows[MBM];

    const int tid = threadIdx.x;
    if (tid < MBM) {
        int r = rowBase + tid;
        Rows[tid] = (r < cnt) ? g_idx[e * TOK + r] : 0;   // clamp: safe read, discarded
    }
    __syncthreads();

    const int colBase = blockIdx.x * MBN;
    const int NT = DMODEL / MBK;             // 48 k-tiles

    PipeCtx c;
    init_ctx_smem(c, smem);
    c.GN = FF;

    const int aRow0 = tid >> 2,         aC40 = (tid & 3) * 4;
    const int aRow1 = (tid + 256) >> 2, aC41 = ((tid + 256) & 3) * 4;
    const int bRow0 = tid >> 5,         bC40 = (tid & 31) * 4;
    const int bRow1 = (tid + 256) >> 5, bC41 = ((tid + 256) & 31) * 4;
    c.aOff0 = (uint32_t)(aRow0 * ASTRIDE + aC40) * 4;
    c.aOff1 = (uint32_t)(aRow1 * ASTRIDE + aC41) * 4;
    c.bOff0 = (uint32_t)(bRow0 * BSTRIDE + bC40) * 4;
    c.bOff1 = (uint32_t)(bRow1 * BSTRIDE + bC41) * 4;
    c.aSrc0 = g_t + (size_t)Rows[aRow0] * DMODEL + aC40;
    c.aSrc1 = g_t + (size_t)Rows[aRow1] * DMODEL + aC41;
    const float* Bw = W1 + (size_t)e * DMODEL * FF + colBase;
    c.bSrc0 = Bw + (size_t)bRow0 * FF + bC40;
    c.bSrc1 = Bw + (size_t)bRow1 * FF + bC41;

    const int wid = tid >> 5, lane = tid & 31;
    const int wm = wid & 1, wn = wid >> 1;
    const int qr = lane >> 2, qc = lane & 3;

    float acc[4][4][4] = {};
    run_pipeline(c, smem, NT, wm, wn, qr, qc, acc);

    const float* b1e = b1 + (size_t)e * FF;
    float* hidE = g_hid + (size_t)e * TOK * FF;
    #pragma unroll
    for (int mt = 0; mt < 4; mt++) {
        int lr0 = wm * 64 + mt * 16 + qr;
        int r0 = rowBase + lr0, r1 = r0 + 8;
        #pragma unroll
        for (int nt = 0; nt < 4; nt++) {
            int cc = colBase + wn * 32 + nt * 8 + qc * 2;
            if (r0 < cnt) {
                float2 o = { gelu_tanh(acc[mt][nt][0] + b1e[cc]),
                             gelu_tanh(acc[mt][nt][1] + b1e[cc + 1]) };
                *(float2*)&hidE[(size_t)r0 * FF + cc] = o;
            }
            if (r1 < cnt) {
                float2 o = { gelu_tanh(acc[mt][nt][2] + b1e[cc]),
                             gelu_tanh(acc[mt][nt][3] + b1e[cc + 1]) };
                *(float2*)&hidE[(size_t)r1 * FF + cc] = o;
            }
        }
    }
}

// ---------------------------------------------------------------------------
// Kernel 4: FFN2 — 4-stage cp.async pipeline, TF32 mma.
//           out[tok] += gate * (hid_e @ W2_e + b2_e); K=FF(1024), N=DMODEL
// ---------------------------------------------------------------------------
__global__ __launch_bounds__(256, 2) void ffn2_mma_kernel(
    const float* __restrict__ W2,
    const float* __restrict__ b2,
    float* __restrict__ out)
{
    const int e = blockIdx.z;
    const int cnt = g_cnt[e];
    const int rowBase = blockIdx.y * MBM;
    if (rowBase >= cnt) return;

    extern __shared__ float smem[];
    __shared__ int   Rows[MBM];
    __shared__ float Gates[MBM];

    const int tid = threadIdx.x;
    if (tid < MBM) {
        int r = rowBase + tid;
        Rows[tid]  = (r < cnt) ? g_idx[e * TOK + r] : 0;
        Gates[tid] = (r < cnt) ? g_gate[e * TOK + r] : 0.f;
    }
    __syncthreads();

    const int colBase = blockIdx.x * MBN;
    const int NT = FF / MBK;                 // 64 k-tiles

    PipeCtx c;
    init_ctx_smem(c, smem);
    c.GN = DMODEL;

    const int aRow0 = tid >> 2,         aC40 = (tid & 3) * 4;
    const int aRow1 = (tid + 256) >> 2, aC41 = ((tid + 256) & 3) * 4;
    const int bRow0 = tid >> 5,         bC40 = (tid & 31) * 4;
    const int bRow1 = (tid + 256) >> 5, bC41 = ((tid + 256) & 31) * 4;
    c.aOff0 = (uint32_t)(aRow0 * ASTRIDE + aC40) * 4;
    c.aOff1 = (uint32_t)(aRow1 * ASTRIDE + aC41) * 4;
    c.bOff0 = (uint32_t)(bRow0 * BSTRIDE + bC40) * 4;
    c.bOff1 = (uint32_t)(bRow1 * BSTRIDE + bC41) * 4;
    const float* hidE = g_hid + (size_t)e * TOK * FF;
    c.aSrc0 = hidE + (size_t)(rowBase + aRow0) * FF + aC40;  // dense; stale rows discarded
    c.aSrc1 = hidE + (size_t)(rowBase + aRow1) * FF + aC41;
    const float* Bw = W2 + (size_t)e * FF * DMODEL + colBase;
    c.bSrc0 = Bw + (size_t)bRow0 * DMODEL + bC40;
    c.bSrc1 = Bw + (size_t)bRow1 * DMODEL + bC41;

    const int wid = tid >> 5, lane = tid & 31;
    const int wm = wid & 1, wn = wid >> 1;
    const int qr = lane >> 2, qc = lane & 3;

    float acc[4][4][4] = {};
    run_pipeline(c, smem, NT, wm, wn, qr, qc, acc);

    const float* b2e = b2 + (size_t)e * DMODEL;
    #pragma unroll
    for (int mt = 0; mt < 4; mt++) {
        int lr0 = wm * 64 + mt * 16 + qr;
        int r0 = rowBase + lr0, r1 = r0 + 8;
        int tok0 = Rows[lr0], tok1 = Rows[lr0 + 8];
        float g0 = Gates[lr0], g1 = Gates[lr0 + 8];
        #pragma unroll
        for (int nt = 0; nt < 4; nt++) {
            int cc = colBase + wn * 32 + nt * 8 + qc * 2;
            if (r0 < cnt) {
                atomicAdd(&out[(size_t)tok0 * DMODEL + cc],
                          g0 * (acc[mt][nt][0] + b2e[cc]));
                atomicAdd(&out[(size_t)tok0 * DMODEL + cc + 1],
                          g0 * (acc[mt][nt][1] + b2e[cc + 1]));
            }
            if (r1 < cnt) {
                atomicAdd(&out[(size_t)tok1 * DMODEL + cc],
                          g1 * (acc[mt][nt][2] + b2e[cc]));
                atomicAdd(&out[(size_t)tok1 * DMODEL + cc + 1],
                          g1 * (acc[mt][nt][3] + b2e[cc + 1]));
            }
        }
    }
}

// ---------------------------------------------------------------------------
// Launch — inputs: input_ids, W, b, Wg, bg, W1, b1, W2, b2
// ---------------------------------------------------------------------------
extern "C" void kernel_launch(void* const* d_in, const int* in_sizes, int n_in,
                              void* d_out, int out_size) {
    const float* x   = (const float*)d_in[0];
    const float* W   = (const float*)d_in[1];
    const float* b   = (const float*)d_in[2];
    const float* Wg  = (const float*)d_in[3];
    const float* bg  = (const float*)d_in[4];
    const float* W1  = (const float*)d_in[5];
    const float* b1  = (const float*)d_in[6];
    const float* W2  = (const float*)d_in[7];
    const float* b2  = (const float*)d_in[8];
    float* out = (float*)d_out;

    static int attrDone = 0;
    if (!attrDone) {
        cudaFuncSetAttribute(ffn1_mma_kernel,
                             cudaFuncAttributeMaxDynamicSharedMemorySize, SMEM_BYTES);
        cudaFuncSetAttribute(ffn2_mma_kernel,
                             cudaFuncAttributeMaxDynamicSharedMemorySize, SMEM_BYTES);
        attrDone = 1;
    }

    cudaMemsetAsync(out, 0, (size_t)out_size * sizeof(float), 0);

    zero_cnt_kernel<<<1, 32>>>();

    {   // t = x @ W + b  (split-TF32 tensor cores, fp32-equivalent)
        dim3 grid(DMODEL / MBN, TOK / MBM);
        proj_mma_kernel<<<grid, 256>>>(x, W, b);
    }

    {   // router
        int warpsPerBlock = 256 / 32;
        int blocks = TOK / warpsPerBlock;
        router_kernel<<<blocks, 256>>>(Wg, bg);
    }

    {   // FFN1: all experts in one launch
        dim3 g1(FF / MBN, TOK / MBM, NEXP);
        ffn1_mma_kernel<<<g1, 256, SMEM_BYTES>>>(W1, b1);
    }
    {   // FFN2: all experts in one launch
        dim3 g2(DMODEL / MBN, TOK / MBM, NEXP);
        ffn2_mma_kernel<<<g2, 256, SMEM_BYTES>>>(W2, b2, out);
    }
}

// round 15
// speedup vs baseline: 3.4015x; 1.0468x over previous
#include <cuda_runtime.h>
#include <cstdint>
#include <math.h>

// Problem constants
#define TOK    16384      // 8 * 2048 tokens
#define DMODEL 768
#define NEXP   4
#define FF     1024

// MMA GEMM tiling (FFN, cp.async pipeline)
#define MBM 128
#define MBN 128
#define MBK 16
#define STAGES 4
#define ASTRIDE 20                 // words per A row in smem (conflict-free)
#define BSTRIDE 136                // words per B row in smem (conflict-free)
#define A_STAGE_WORDS (MBM * ASTRIDE)       // 2560
#define B_STAGE_WORDS (MBK * BSTRIDE)       // 2176
#define SMEM_BYTES ((STAGES * (A_STAGE_WORDS + B_STAGE_WORDS)) * 4)  // 75776

// proj (split-TF32) tiling
#define PBK 8
#define PAPAD 4
#define PBPAD 8

#define W_ELEMS ((size_t)NEXP * DMODEL * FF)   // 3,145,728 per weight tensor

// Static device scratch (allocations forbidden; zero-initialized at load)
__device__ float    g_t[(size_t)TOK * DMODEL];        // post-projection tokens (fp32, router)
__device__ unsigned g_tc[(size_t)TOK * DMODEL];       // tf32 bits of g_t (MMA operand)
__device__ unsigned g_hid[(size_t)NEXP * TOK * FF];   // per-expert hidden, tf32 bits
__device__ unsigned g_w1c[W_ELEMS];                   // W1 tf32 bits
__device__ unsigned g_w2c[W_ELEMS];                   // W2 tf32 bits
__device__ int      g_idx[NEXP * TOK];                // gathered token ids per expert
__device__ float    g_gate[NEXP * TOK];               // gate per gathered slot
__device__ int      g_cnt[NEXP];                      // tokens per expert

__device__ __forceinline__ float gelu_tanh(float x) {
    float u = 0.7978845608028654f * (x + 0.044715f * x * x * x);
    return 0.5f * x * (1.0f + tanhf(u));
}

__device__ __forceinline__ unsigned f2tf32(float x) {
    unsigned u;
    asm("cvt.rna.tf32.f32 %0, %1;" : "=r"(u) : "f"(x));
    return u;
}

__device__ __forceinline__ void mma_tf32(float* c, const unsigned* a,
                                         unsigned b0, unsigned b1) {
    asm volatile(
        "mma.sync.aligned.m16n8k8.row.col.f32.tf32.tf32.f32 "
        "{%0,%1,%2,%3}, {%4,%5,%6,%7}, {%8,%9}, {%0,%1,%2,%3};"
        : "+f"(c[0]), "+f"(c[1]), "+f"(c[2]), "+f"(c[3])
        : "r"(a[0]), "r"(a[1]), "r"(a[2]), "r"(a[3]), "r"(b0), "r"(b1));
}

__device__ __forceinline__ void cp_async16(uint32_t saddr, const void* gptr) {
    asm volatile("cp.async.cg.shared.global [%0], [%1], 16;"
                 :: "r"(saddr), "l"(gptr));
}
__device__ __forceinline__ void cp_commit() {
    asm volatile("cp.async.commit_group;");
}
__device__ __forceinline__ void cp_wait2() {
    asm volatile("cp.async.wait_group 2;");
}

// ---------------------------------------------------------------------------
// FFN pipeline helpers — all operands are pre-converted tf32 bit patterns.
// ---------------------------------------------------------------------------
struct PipeCtx {
    uint32_t sA[STAGES];
    uint32_t sB[STAGES];
    uint32_t aOff0, aOff1, bOff0, bOff1;
    const unsigned* aSrc0;
    const unsigned* aSrc1;
    const unsigned* bSrc0;
    const unsigned* bSrc1;
    int GN;                      // B gmem row stride
};

__device__ __forceinline__ void issue_stage(const PipeCtx& c, int slot, int kt) {
    cp_async16(c.sA[slot] + c.aOff0, c.aSrc0 + (size_t)kt * MBK);
    cp_async16(c.sA[slot] + c.aOff1, c.aSrc1 + (size_t)kt * MBK);
    cp_async16(c.sB[slot] + c.bOff0, c.bSrc0 + (size_t)kt * MBK * c.GN);
    cp_async16(c.sB[slot] + c.bOff1, c.bSrc1 + (size_t)kt * MBK * c.GN);
}

__device__ __forceinline__ void compute_stage(const unsigned* __restrict__ smA,
                                              const unsigned* __restrict__ smB,
                                              int wm, int wn, int qr, int qc,
                                              float (&acc)[4][4][4]) {
    #pragma unroll
    for (int ks = 0; ks < MBK; ks += 8) {
        unsigned af[4][4];
        #pragma unroll
        for (int mt = 0; mt < 4; mt++) {
            int r0 = wm * 64 + mt * 16 + qr;
            af[mt][0] = smA[r0 * ASTRIDE + ks + qc];
            af[mt][1] = smA[(r0 + 8) * ASTRIDE + ks + qc];
            af[mt][2] = smA[r0 * ASTRIDE + ks + qc + 4];
            af[mt][3] = smA[(r0 + 8) * ASTRIDE + ks + qc + 4];
        }
        #pragma unroll
        for (int nt = 0; nt < 4; nt++) {
            int c0 = wn * 32 + nt * 8 + qr;
            unsigned b0  = smB[(ks + qc) * BSTRIDE + c0];
            unsigned b1v = smB[(ks + qc + 4) * BSTRIDE + c0];
            #pragma unroll
            for (int mt = 0; mt < 4; mt++)
                mma_tf32(acc[mt][nt], af[mt], b0, b1v);
        }
    }
}

// Runs the full K loop (NT tiles, NT % STAGES == 0) over the pipeline.
__device__ __forceinline__ void run_pipeline(const PipeCtx& c,
                                             const unsigned* __restrict__ smem,
                                             int NT, int wm, int wn,
                                             int qr, int qc,
                                             float (&acc)[4][4][4]) {
    #pragma unroll
    for (int s = 0; s < STAGES - 1; s++) {
        issue_stage(c, s, s);
        cp_commit();
    }
    for (int base = 0; base < NT; base += STAGES) {
        #pragma unroll
        for (int s = 0; s < STAGES; s++) {
            const int ktc = base + s;
            cp_wait2();
            __syncthreads();
            const int kp = ktc + STAGES - 1;
            if (kp < NT) issue_stage(c, (s + STAGES - 1) % STAGES, kp);
            cp_commit();
            const unsigned* smA = smem + s * A_STAGE_WORDS;
            const unsigned* smB = smem + STAGES * A_STAGE_WORDS + s * B_STAGE_WORDS;
            compute_stage(smA, smB, wm, wn, qr, qc, acc);
        }
    }
}

__device__ __forceinline__ void init_ctx_smem(PipeCtx& c, const unsigned* smem) {
    uint32_t smemBase = (uint32_t)__cvta_generic_to_shared(smem);
    #pragma unroll
    for (int s = 0; s < STAGES; s++) {
        c.sA[s] = smemBase + s * A_STAGE_WORDS * 4;
        c.sB[s] = smemBase + (STAGES * A_STAGE_WORDS + s * B_STAGE_WORDS) * 4;
    }
}

// ---------------------------------------------------------------------------
// Kernel 0: reset per-launch state
// ---------------------------------------------------------------------------
__global__ void zero_cnt_kernel() {
    if (threadIdx.x < NEXP) g_cnt[threadIdx.x] = 0;
}

// ---------------------------------------------------------------------------
// Kernel 0b: pre-convert W1, W2 to tf32 bit patterns (vectorized grid-stride)
// ---------------------------------------------------------------------------
__global__ void cvt_weights_kernel(const float* __restrict__ W1,
                                   const float* __restrict__ W2) {
    size_t n4 = W_ELEMS / 4;
    size_t stride = (size_t)gridDim.x * blockDim.x;
    for (size_t i = (size_t)blockIdx.x * blockDim.x + threadIdx.x; i < n4; i += stride) {
        float4 w1 = ((const float4*)W1)[i];
        uint4 c1 = { f2tf32(w1.x), f2tf32(w1.y), f2tf32(w1.z), f2tf32(w1.w) };
        ((uint4*)g_w1c)[i] = c1;
        float4 w2 = ((const float4*)W2)[i];
        uint4 c2 = { f2tf32(w2.x), f2tf32(w2.y), f2tf32(w2.z), f2tf32(w2.w) };
        ((uint4*)g_w2c)[i] = c2;
    }
}

// ---------------------------------------------------------------------------
// Kernel 1: t = input @ W + b  (split-TF32 tensor cores, fp32-equivalent;
//           router precision depends on it). Also emits g_tc = tf32(t).
// ---------------------------------------------------------------------------
__global__ __launch_bounds__(256, 2) void proj_mma_kernel(
    const float* __restrict__ A,
    const float* __restrict__ Wm,
    const float* __restrict__ bias)
{
    __shared__ unsigned Ash[2][MBM][PBK + PAPAD];
    __shared__ unsigned Asl[2][MBM][PBK + PAPAD];
    __shared__ unsigned Bsh[2][PBK][MBN + PBPAD];
    __shared__ unsigned Bsl[2][PBK][MBN + PBPAD];

    const int tid = threadIdx.x;
    const int rowBase = blockIdx.y * MBM;
    const int colBase = blockIdx.x * MBN;
    const int K = DMODEL, N = DMODEL;

    const int aRow = tid >> 1, aC4 = (tid & 1) * 4;
    const int bRow = tid >> 5, bC4 = (tid & 31) * 4;
    const float* aP = A + (size_t)(rowBase + aRow) * K + aC4;
    const float* bP = Wm + (size_t)bRow * N + colBase + bC4;

    const int wid = tid >> 5, lane = tid & 31;
    const int wm = wid & 1, wn = wid >> 1;
    const int qr = lane >> 2, qc = lane & 3;

    float acc[4][4][4] = {};
    float4 aReg = *(const float4*)aP;
    float4 bReg = *(const float4*)bP;

    auto proj_store = [&](int bi) {
        uint4 ah, al, bh, bl;
        ah.x = f2tf32(aReg.x); al.x = f2tf32(aReg.x - __uint_as_float(ah.x));
        ah.y = f2tf32(aReg.y); al.y = f2tf32(aReg.y - __uint_as_float(ah.y));
        ah.z = f2tf32(aReg.z); al.z = f2tf32(aReg.z - __uint_as_float(ah.z));
        ah.w = f2tf32(aReg.w); al.w = f2tf32(aReg.w - __uint_as_float(ah.w));
        *(uint4*)&Ash[bi][aRow][aC4] = ah;
        *(uint4*)&Asl[bi][aRow][aC4] = al;
        bh.x = f2tf32(bReg.x); bl.x = f2tf32(bReg.x - __uint_as_float(bh.x));
        bh.y = f2tf32(bReg.y); bl.y = f2tf32(bReg.y - __uint_as_float(bh.y));
        bh.z = f2tf32(bReg.z); bl.z = f2tf32(bReg.z - __uint_as_float(bh.z));
        bh.w = f2tf32(bReg.w); bl.w = f2tf32(bReg.w - __uint_as_float(bh.w));
        *(uint4*)&Bsh[bi][bRow][bC4] = bh;
        *(uint4*)&Bsl[bi][bRow][bC4] = bl;
    };

    proj_store(0);
    __syncthreads();

    int buf = 0;
    for (int k0 = 0; k0 < K; k0 += PBK) {
        const bool nxt = (k0 + PBK) < K;
        if (nxt) {
            aReg = *(const float4*)(aP + k0 + PBK);
            bReg = *(const float4*)(bP + (size_t)(k0 + PBK) * N);
        }

        unsigned ahi[4][4], alo[4][4];
        #pragma unroll
        for (int mt = 0; mt < 4; mt++) {
            int r0 = wm * 64 + mt * 16 + qr;
            ahi[mt][0] = Ash[buf][r0][qc];     ahi[mt][1] = Ash[buf][r0 + 8][qc];
            ahi[mt][2] = Ash[buf][r0][qc + 4]; ahi[mt][3] = Ash[buf][r0 + 8][qc + 4];
            alo[mt][0] = Asl[buf][r0][qc];     alo[mt][1] = Asl[buf][r0 + 8][qc];
            alo[mt][2] = Asl[buf][r0][qc + 4]; alo[mt][3] = Asl[buf][r0 + 8][qc + 4];
        }
        #pragma unroll
        for (int nt = 0; nt < 4; nt++) {
            int c0 = wn * 32 + nt * 8 + qr;
            unsigned bh0 = Bsh[buf][qc][c0], bh1 = Bsh[buf][qc + 4][c0];
            unsigned bl0 = Bsl[buf][qc][c0], bl1 = Bsl[buf][qc + 4][c0];
            #pragma unroll
            for (int mt = 0; mt < 4; mt++) {
                mma_tf32(acc[mt][nt], ahi[mt], bh0, bh1);
                mma_tf32(acc[mt][nt], alo[mt], bh0, bh1);
                mma_tf32(acc[mt][nt], ahi[mt], bl0, bl1);
            }
        }

        if (nxt) proj_store(buf ^ 1);
        __syncthreads();
        buf ^= 1;
    }

    #pragma unroll
    for (int mt = 0; mt < 4; mt++) {
        int r0 = rowBase + wm * 64 + mt * 16 + qr;
        int r1 = r0 + 8;
        #pragma unroll
        for (int nt = 0; nt < 4; nt++) {
            int c = colBase + wn * 32 + nt * 8 + qc * 2;
            float v00 = acc[mt][nt][0] + bias[c];
            float v01 = acc[mt][nt][1] + bias[c + 1];
            float v10 = acc[mt][nt][2] + bias[c];
            float v11 = acc[mt][nt][3] + bias[c + 1];
            *(float2*)&g_t[(size_t)r0 * DMODEL + c] = make_float2(v00, v01);
            *(float2*)&g_t[(size_t)r1 * DMODEL + c] = make_float2(v10, v11);
            uint2 c0v = { f2tf32(v00), f2tf32(v01) };
            uint2 c1v = { f2tf32(v10), f2tf32(v11) };
            *(uint2*)&g_tc[(size_t)r0 * DMODEL + c] = c0v;
            *(uint2*)&g_tc[(size_t)r1 * DMODEL + c] = c1v;
        }
    }
}

// ---------------------------------------------------------------------------
// Kernel 2: router — warp per token, top-2, renormalized gates, gather lists
// ---------------------------------------------------------------------------
__global__ void router_kernel(const float* __restrict__ Wg,
                              const float* __restrict__ bg)
{
    int warp = (blockIdx.x * blockDim.x + threadIdx.x) >> 5;
    int lane = threadIdx.x & 31;
    if (warp >= TOK) return;

    const float* row = g_t + (size_t)warp * DMODEL;
    float l0 = 0.f, l1 = 0.f, l2 = 0.f, l3 = 0.f;
    for (int k = lane; k < DMODEL; k += 32) {
        float x = row[k];
        const float* w = Wg + k * NEXP;
        l0 += x * w[0]; l1 += x * w[1]; l2 += x * w[2]; l3 += x * w[3];
    }
    #pragma unroll
    for (int off = 16; off; off >>= 1) {
        l0 += __shfl_xor_sync(0xFFFFFFFFu, l0, off);
        l1 += __shfl_xor_sync(0xFFFFFFFFu, l1, off);
        l2 += __shfl_xor_sync(0xFFFFFFFFu, l2, off);
        l3 += __shfl_xor_sync(0xFFFFFFFFu, l3, off);
    }
    if (lane == 0) {
        float v[NEXP] = { l0 + bg[0], l1 + bg[1], l2 + bg[2], l3 + bg[3] };
        int i1 = 0;
        #pragma unroll
        for (int e = 1; e < NEXP; e++) if (v[e] > v[i1]) i1 = e;
        int i2 = -1;
        #pragma unroll
        for (int e = 0; e < NEXP; e++) {
            if (e == i1) continue;
            if (i2 < 0 || v[e] > v[i2]) i2 = e;
        }
        float gb = expf(v[i2] - v[i1]);
        float s = 1.0f + gb;
        float ga = 1.0f / s;
        gb = gb / s;

        int p1 = atomicAdd(&g_cnt[i1], 1);
        g_idx[i1 * TOK + p1]  = warp;
        g_gate[i1 * TOK + p1] = ga;
        int p2 = atomicAdd(&g_cnt[i2], 1);
        g_idx[i2 * TOK + p2]  = warp;
        g_gate[i2 * TOK + p2] = gb;
    }
}

// ---------------------------------------------------------------------------
// Kernel 3: FFN1 — 4-stage cp.async pipeline, TF32 mma, no mainloop cvt.
//           hid_e = tf32(gelu(t[gather_e] @ W1_e + b1_e)); K=DMODEL, N=FF
// ---------------------------------------------------------------------------
__global__ __launch_bounds__(256, 2) void ffn1_mma_kernel(
    const float* __restrict__ b1)
{
    const int e = blockIdx.z;
    const int cnt = g_cnt[e];
    const int rowBase = blockIdx.y * MBM;
    if (rowBase >= cnt) return;

    extern __shared__ unsigned smem[];
    __shared__ int Rows[MBM];

    const int tid = threadIdx.x;
    if (tid < MBM) {
        int r = rowBase + tid;
        Rows[tid] = (r < cnt) ? g_idx[e * TOK + r] : 0;   // clamp: safe read, discarded
    }
    __syncthreads();

    const int colBase = blockIdx.x * MBN;
    const int NT = DMODEL / MBK;             // 48 k-tiles

    PipeCtx c;
    init_ctx_smem(c, smem);
    c.GN = FF;

    const int aRow0 = tid >> 2,         aC40 = (tid & 3) * 4;
    const int aRow1 = (tid + 256) >> 2, aC41 = ((tid + 256) & 3) * 4;
    const int bRow0 = tid >> 5,         bC40 = (tid & 31) * 4;
    const int bRow1 = (tid + 256) >> 5, bC41 = ((tid + 256) & 31) * 4;
    c.aOff0 = (uint32_t)(aRow0 * ASTRIDE + aC40) * 4;
    c.aOff1 = (uint32_t)(aRow1 * ASTRIDE + aC41) * 4;
    c.bOff0 = (uint32_t)(bRow0 * BSTRIDE + bC40) * 4;
    c.bOff1 = (uint32_t)(bRow1 * BSTRIDE + bC41) * 4;
    c.aSrc0 = g_tc + (size_t)Rows[aRow0] * DMODEL + aC40;
    c.aSrc1 = g_tc + (size_t)Rows[aRow1] * DMODEL + aC41;
    const unsigned* Bw = g_w1c + (size_t)e * DMODEL * FF + colBase;
    c.bSrc0 = Bw + (size_t)bRow0 * FF + bC40;
    c.bSrc1 = Bw + (size_t)bRow1 * FF + bC41;

    const int wid = tid >> 5, lane = tid & 31;
    const int wm = wid & 1, wn = wid >> 1;
    const int qr = lane >> 2, qc = lane & 3;

    float acc[4][4][4] = {};
    run_pipeline(c, smem, NT, wm, wn, qr, qc, acc);

    const float* b1e = b1 + (size_t)e * FF;
    unsigned* hidE = g_hid + (size_t)e * TOK * FF;
    #pragma unroll
    for (int mt = 0; mt < 4; mt++) {
        int lr0 = wm * 64 + mt * 16 + qr;
        int r0 = rowBase + lr0, r1 = r0 + 8;
        #pragma unroll
        for (int nt = 0; nt < 4; nt++) {
            int cc = colBase + wn * 32 + nt * 8 + qc * 2;
            if (r0 < cnt) {
                uint2 o = { f2tf32(gelu_tanh(acc[mt][nt][0] + b1e[cc])),
                            f2tf32(gelu_tanh(acc[mt][nt][1] + b1e[cc + 1])) };
                *(uint2*)&hidE[(size_t)r0 * FF + cc] = o;
            }
            if (r1 < cnt) {
                uint2 o = { f2tf32(gelu_tanh(acc[mt][nt][2] + b1e[cc])),
                            f2tf32(gelu_tanh(acc[mt][nt][3] + b1e[cc + 1])) };
                *(uint2*)&hidE[(size_t)r1 * FF + cc] = o;
            }
        }
    }
}

// ---------------------------------------------------------------------------
// Kernel 4: FFN2 — 4-stage cp.async pipeline, TF32 mma, no mainloop cvt.
//           out[tok] += gate * (hid_e @ W2_e + b2_e); K=FF, N=DMODEL
// ---------------------------------------------------------------------------
__global__ __launch_bounds__(256, 2) void ffn2_mma_kernel(
    const float* __restrict__ b2,
    float* __restrict__ out)
{
    const int e = blockIdx.z;
    const int cnt = g_cnt[e];
    const int rowBase = blockIdx.y * MBM;
    if (rowBase >= cnt) return;

    extern __shared__ unsigned smem[];
    __shared__ int   Rows[MBM];
    __shared__ float Gates[MBM];

    const int tid = threadIdx.x;
    if (tid < MBM) {
        int r = rowBase + tid;
        Rows[tid]  = (r < cnt) ? g_idx[e * TOK + r] : 0;
        Gates[tid] = (r < cnt) ? g_gate[e * TOK + r] : 0.f;
    }
    __syncthreads();

    const int colBase = blockIdx.x * MBN;
    const int NT = FF / MBK;                 // 64 k-tiles

    PipeCtx c;
    init_ctx_smem(c, smem);
    c.GN = DMODEL;

    const int aRow0 = tid >> 2,         aC40 = (tid & 3) * 4;
    const int aRow1 = (tid + 256) >> 2, aC41 = ((tid + 256) & 3) * 4;
    const int bRow0 = tid >> 5,         bC40 = (tid & 31) * 4;
    const int bRow1 = (tid + 256) >> 5, bC41 = ((tid + 256) & 31) * 4;
    c.aOff0 = (uint32_t)(aRow0 * ASTRIDE + aC40) * 4;
    c.aOff1 = (uint32_t)(aRow1 * ASTRIDE + aC41) * 4;
    c.bOff0 = (uint32_t)(bRow0 * BSTRIDE + bC40) * 4;
    c.bOff1 = (uint32_t)(bRow1 * BSTRIDE + bC41) * 4;
    const unsigned* hidE = g_hid + (size_t)e * TOK * FF;
    c.aSrc0 = hidE + (size_t)(rowBase + aRow0) * FF + aC40;  // dense; stale rows discarded
    c.aSrc1 = hidE + (size_t)(rowBase + aRow1) * FF + aC41;
    const unsigned* Bw = g_w2c + (size_t)e * FF * DMODEL + colBase;
    c.bSrc0 = Bw + (size_t)bRow0 * DMODEL + bC40;
    c.bSrc1 = Bw + (size_t)bRow1 * DMODEL + bC41;

    const int wid = tid >> 5, lane = tid & 31;
    const int wm = wid & 1, wn = wid >> 1;
    const int qr = lane >> 2, qc = lane & 3;

    float acc[4][4][4] = {};
    run_pipeline(c, smem, NT, wm, wn, qr, qc, acc);

    const float* b2e = b2 + (size_t)e * DMODEL;
    #pragma unroll
    for (int mt = 0; mt < 4; mt++) {
        int lr0 = wm * 64 + mt * 16 + qr;
        int r0 = rowBase + lr0, r1 = r0 + 8;
        int tok0 = Rows[lr0], tok1 = Rows[lr0 + 8];
        float g0 = Gates[lr0], g1 = Gates[lr0 + 8];
        #pragma unroll
        for (int nt = 0; nt < 4; nt++) {
            int cc = colBase + wn * 32 + nt * 8 + qc * 2;
            if (r0 < cnt) {
                atomicAdd(&out[(size_t)tok0 * DMODEL + cc],
                          g0 * (acc[mt][nt][0] + b2e[cc]));
                atomicAdd(&out[(size_t)tok0 * DMODEL + cc + 1],
                          g0 * (acc[mt][nt][1] + b2e[cc + 1]));
            }
            if (r1 < cnt) {
                atomicAdd(&out[(size_t)tok1 * DMODEL + cc],
                          g1 * (acc[mt][nt][2] + b2e[cc]));
                atomicAdd(&out[(size_t)tok1 * DMODEL + cc + 1],
                          g1 * (acc[mt][nt][3] + b2e[cc + 1]));
            }
        }
    }
}

// ---------------------------------------------------------------------------
// Launch — inputs: input_ids, W, b, Wg, bg, W1, b1, W2, b2
// ---------------------------------------------------------------------------
extern "C" void kernel_launch(void* const* d_in, const int* in_sizes, int n_in,
                              void* d_out, int out_size) {
    const float* x   = (const float*)d_in[0];
    const float* W   = (const float*)d_in[1];
    const float* b   = (const float*)d_in[2];
    const float* Wg  = (const float*)d_in[3];
    const float* bg  = (const float*)d_in[4];
    const float* W1  = (const float*)d_in[5];
    const float* b1  = (const float*)d_in[6];
    const float* W2  = (const float*)d_in[7];
    const float* b2  = (const float*)d_in[8];
    float* out = (float*)d_out;

    static int attrDone = 0;
    if (!attrDone) {
        cudaFuncSetAttribute(ffn1_mma_kernel,
                             cudaFuncAttributeMaxDynamicSharedMemorySize, SMEM_BYTES);
        cudaFuncSetAttribute(ffn2_mma_kernel,
                             cudaFuncAttributeMaxDynamicSharedMemorySize, SMEM_BYTES);
        attrDone = 1;
    }

    cudaMemsetAsync(out, 0, (size_t)out_size * sizeof(float), 0);

    zero_cnt_kernel<<<1, 32>>>();
    cvt_weights_kernel<<<592, 256>>>(W1, W2);

    {   // t = x @ W + b  (split-TF32 tensor cores, fp32-equivalent)
        dim3 grid(DMODEL / MBN, TOK / MBM);
        proj_mma_kernel<<<grid, 256>>>(x, W, b);
    }

    {   // router
        int warpsPerBlock = 256 / 32;
        int blocks = TOK / warpsPerBlock;
        router_kernel<<<blocks, 256>>>(Wg, bg);
    }

    {   // FFN1: all experts in one launch
        dim3 g1(FF / MBN, TOK / MBM, NEXP);
        ffn1_mma_kernel<<<g1, 256, SMEM_BYTES>>>(b1);
    }
    {   // FFN2: all experts in one launch
        dim3 g2(DMODEL / MBN, TOK / MBM, NEXP);
        ffn2_mma_kernel<<<g2, 256, SMEM_BYTES>>>(b2, out);
    }
}